// round 15
// baseline (speedup 1.0000x reference)
#include <cuda_runtime.h>
#include <cstdint>

#define Bq 4
#define Cc 512
#define NPIX 9216
#define ICd 128
#define Hd 96
#define Wd 96
#define ESPLIT 4

// ---------------- scratch ----------------
__device__ float g_xr[(size_t)Bq * Cc * NPIX];    // tf32-rounded x
__device__ float g_out1[Bq * ICd * NPIX];
__device__ float g_qkv[(size_t)Bq * 192 * NPIX];  // rows: 0-15 q, 16-31 k, 32-159 v
__device__ float g_cca[Bq * ICd * NPIX];
__device__ float g_out2[Bq * ICd * NPIX];
__device__ float g_bott1[(size_t)Bq * Cc * NPIX];
__device__ float g_energy[Bq * Cc * Cc];
__device__ float g_epart[(size_t)ESPLIT * Bq * Cc * Cc];
__device__ float g_wta[9 * 128 * 512];
__device__ float g_wtb[9 * 128 * 128];
__device__ float g_wt1[9 * 512 * 640];
__device__ float g_w2r[512 * 512];
__device__ float g_wqkv[192 * 128];
__device__ float g_bqkv[192];

__device__ __forceinline__ float tf32r(float x) {
    uint32_t u;
    asm("cvt.rna.tf32.f32 %0, %1;" : "=r"(u) : "f"(x));
    return __uint_as_float(u);
}

__device__ __forceinline__ void mma1688(float* c, const uint32_t* a, const uint32_t* b) {
    asm volatile(
        "mma.sync.aligned.m16n8k8.row.col.f32.tf32.tf32.f32 "
        "{%0,%1,%2,%3}, {%4,%5,%6,%7}, {%8,%9}, {%0,%1,%2,%3};"
        : "+f"(c[0]), "+f"(c[1]), "+f"(c[2]), "+f"(c[3])
        : "r"(a[0]), "r"(a[1]), "r"(a[2]), "r"(a[3]), "r"(b[0]), "r"(b[1]));
}

// ---------------- prep ----------------
__global__ void roundcopy4(const float* __restrict__ s, float* __restrict__ d, int n4) {
    for (int i = blockIdx.x * blockDim.x + threadIdx.x; i < n4; i += gridDim.x * blockDim.x) {
        float4 v = ((const float4*)s)[i];
        v.x = tf32r(v.x); v.y = tf32r(v.y); v.z = tf32r(v.z); v.w = tf32r(v.w);
        ((float4*)d)[i] = v;
    }
}

__global__ void prep_weights(const float* __restrict__ wa, const float* __restrict__ wb,
                             const float* __restrict__ w1, const float* __restrict__ w2,
                             const float* __restrict__ wq, const float* __restrict__ bq,
                             const float* __restrict__ wk, const float* __restrict__ bk,
                             const float* __restrict__ wv, const float* __restrict__ bv)
{
    const int n1 = 128 * 512 * 9;
    const int n2 = 128 * 128 * 9;
    const int n3 = 512 * 640 * 9;
    const int n4 = 512 * 512;
    const int n5 = 192 * 128;
    const int ntot = n1 + n2 + n3 + n4 + n5 + 192;
    for (int i = blockIdx.x * blockDim.x + threadIdx.x; i < ntot; i += gridDim.x * blockDim.x) {
        if (i < n1) {
            int oc = i / (512 * 9);
            int rem = i - oc * (512 * 9);
            int ic = rem / 9, tap = rem - ic * 9;
            g_wta[((size_t)tap * 128 + oc) * 512 + ic] = tf32r(wa[i]);
        } else if (i < n1 + n2) {
            int j = i - n1;
            int oc = j / (128 * 9);
            int rem = j - oc * (128 * 9);
            int ic = rem / 9, tap = rem - ic * 9;
            g_wtb[((size_t)tap * 128 + oc) * 128 + ic] = tf32r(wb[j]);
        } else if (i < n1 + n2 + n3) {
            int j = i - n1 - n2;
            int oc = j / (640 * 9);
            int rem = j - oc * (640 * 9);
            int ic = rem / 9, tap = rem - ic * 9;
            g_wt1[((size_t)tap * 512 + oc) * 640 + ic] = tf32r(w1[j]);
        } else if (i < n1 + n2 + n3 + n4) {
            int j = i - n1 - n2 - n3;
            g_w2r[j] = tf32r(w2[j]);
        } else if (i < n1 + n2 + n3 + n4 + n5) {
            int j = i - n1 - n2 - n3 - n4;
            int r = j >> 7, ic = j & 127;
            float v = 0.f;
            if (r < 16) v = wq[r * 128 + ic];
            else if (r < 32) v = wk[(r - 16) * 128 + ic];
            else if (r < 160) v = wv[(r - 32) * 128 + ic];
            g_wqkv[j] = tf32r(v);
        } else {
            int r = i - n1 - n2 - n3 - n4 - n5;
            float v = 0.f;
            if (r < 16) v = bq[r];
            else if (r < 32) v = bk[r - 16];
            else if (r < 160) v = bv[r - 32];
            g_bqkv[r] = v;
        }
    }
}

// ---------------- tf32 TC implicit-GEMM conv (+BN+ReLU) ----------------
// CTA: 128 oc x 128 px, 8 warps of 64x32, 2 CTAs/SM.
// A perm-K (stride 20); B perm-K XOR-swizzled [px][16]; double-buffered.
#define ASTRIDE 20
#define ASTG (128 * ASTRIDE)
#define BSTG (128 * 16)
#define CONV_SMEM ((2 * ASTG + 2 * BSTG) * 4)

template<int NTAPS, bool ROUND>
__global__ void __launch_bounds__(256, 2) conv_tc(
    const float* __restrict__ in1, int cin1,
    const float* __restrict__ in2, int cin2,
    const float* __restrict__ Aw, int OCtot,
    float* __restrict__ outp,
    const float* __restrict__ q0, const float* __restrict__ q1,
    const float* __restrict__ q2, const float* __restrict__ q3)
{
    const int CIN = cin1 + cin2;
    const int NCHUNK = (NTAPS * CIN) / 16;

    extern __shared__ float dsm[];
    float* Asm = dsm;
    float* Bsm = dsm + 2 * ASTG;

    int tid = threadIdx.x, lane = tid & 31, wid = tid >> 5;
    int wm = (wid & 1) * 64, wn = (wid >> 1) * 32;
    int px0 = blockIdx.x * 128;
    int oc0 = blockIdx.y * 128;
    int b = blockIdx.z;
    in1 += (size_t)b * cin1 * NPIX;
    if (cin2 > 0) in2 += (size_t)b * cin2 * NPIX;
    outp += (size_t)b * OCtot * NPIX;

    int arow = tid >> 1, ahalf = tid & 1;
    int pxl = tid & 127;
    int khalf = tid >> 7;                 // 0: slots 0,1 ; 1: slots 2,3
    int px = px0 + pxl;
    int ph = px / 96, pw = px - ph * 96;
    int rswB = (pxl >> 1) & 3;
    int kq = lane & 3, g4 = lane >> 2;

    float4 pa0, pa1;
    float pb[8];

    auto loadA = [&](int c) {
        int ko = c * 16;
        int tap = (NTAPS == 9) ? ko / CIN : 0;
        int ic = ko - tap * CIN;
        const float* ap = Aw + ((size_t)tap * OCtot + oc0 + arow) * CIN + ic + ahalf * 8;
        pa0 = *(const float4*)ap;
        pa1 = *(const float4*)(ap + 4);
    };
    auto loadB = [&](int c) {
        int ko = c * 16;
        int tap = (NTAPS == 9) ? ko / CIN : 0;
        int ic = ko - tap * CIN;
        const float* src = (ic < cin1) ? (in1 + (size_t)ic * NPIX)
                                       : (in2 + (size_t)(ic - cin1) * NPIX);
        bool ok = true;
        const float* sp;
        if (NTAPS == 9) {
            int dh = tap / 3 - 1, dw = tap % 3 - 1;
            int hh = ph + dh, ww = pw + dw;
            ok = ((unsigned)hh < 96u) && ((unsigned)ww < 96u);
            sp = src + px + dh * 96 + dw;
        } else {
            sp = src + px;
        }
#pragma unroll
        for (int t2 = 0; t2 < 2; t2++) {
            int slot = khalf * 2 + t2;
#pragma unroll
            for (int u = 0; u < 4; u++)
                pb[t2 * 4 + u] = ok ? __ldg(sp + (size_t)(slot + u * 4) * NPIX) : 0.f;
        }
    };
    auto storeAB = [&](int sl) {
        float* Ad = Asm + sl * ASTG + arow * ASTRIDE + ahalf * 2;
        float av0[4] = {pa0.x, pa0.y, pa0.z, pa0.w};
        float av1[4] = {pa1.x, pa1.y, pa1.z, pa1.w};
#pragma unroll
        for (int t = 0; t < 4; t++)
            *(float2*)(Ad + t * 4) = make_float2(av0[t], av1[t]);
        float* Bd = Bsm + sl * BSTG + pxl * 16;
#pragma unroll
        for (int t2 = 0; t2 < 2; t2++) {
            int slot = khalf * 2 + t2;
            *(float4*)(Bd + ((slot ^ rswB) * 4)) =
                make_float4(pb[t2 * 4 + 0], pb[t2 * 4 + 1], pb[t2 * 4 + 2], pb[t2 * 4 + 3]);
        }
    };

    float acc[4][4][4];
#pragma unroll
    for (int i = 0; i < 4; i++)
#pragma unroll
        for (int j = 0; j < 4; j++)
#pragma unroll
            for (int r = 0; r < 4; r++) acc[i][j][r] = 0.f;

    auto doMMA = [&](int sl) {
        const float* Ab = Asm + sl * ASTG;
        const float* Bb = Bsm + sl * BSTG;
        float4 alo[4], ahi[4], bfr[4];
#pragma unroll
        for (int i = 0; i < 4; i++) {
            int m = wm + i * 16 + g4;
            alo[i] = *(const float4*)(Ab + m * ASTRIDE + kq * 4);
            ahi[i] = *(const float4*)(Ab + (m + 8) * ASTRIDE + kq * 4);
        }
#pragma unroll
        for (int j = 0; j < 4; j++) {
            int n = wn + j * 8 + g4;
            int slot = kq ^ ((n >> 1) & 3);
            bfr[j] = *(const float4*)(Bb + n * 16 + slot * 4);
        }
#pragma unroll
        for (int kk = 0; kk < 2; kk++) {
#pragma unroll
            for (int i = 0; i < 4; i++) {
                uint32_t af[4];
                if (kk == 0) {
                    af[0] = __float_as_uint(alo[i].x); af[1] = __float_as_uint(ahi[i].x);
                    af[2] = __float_as_uint(alo[i].y); af[3] = __float_as_uint(ahi[i].y);
                } else {
                    af[0] = __float_as_uint(alo[i].z); af[1] = __float_as_uint(ahi[i].z);
                    af[2] = __float_as_uint(alo[i].w); af[3] = __float_as_uint(ahi[i].w);
                }
#pragma unroll
                for (int j = 0; j < 4; j++) {
                    uint32_t bu[2];
                    if (kk == 0) { bu[0] = __float_as_uint(bfr[j].x); bu[1] = __float_as_uint(bfr[j].y); }
                    else         { bu[0] = __float_as_uint(bfr[j].z); bu[1] = __float_as_uint(bfr[j].w); }
                    mma1688(acc[i][j], af, bu);
                }
            }
        }
    };

    loadA(0); loadB(0); storeAB(0);
    __syncthreads();

    for (int c = 0; c < NCHUNK; c++) {
        int s = c & 1;
        if (c + 1 < NCHUNK) { loadA(c + 1); loadB(c + 1); }
        doMMA(s);
        if (c + 1 < NCHUNK) storeAB(s ^ 1);
        __syncthreads();
    }

#pragma unroll
    for (int i = 0; i < 4; i++) {
#pragma unroll
        for (int hh = 0; hh < 2; hh++) {
            int row = oc0 + wm + i * 16 + g4 + hh * 8;
            float inv = __ldg(q0 + row) * rsqrtf(__ldg(q3 + row) + 1e-5f);
            float add = __ldg(q1 + row) - __ldg(q2 + row) * inv;
#pragma unroll
            for (int j = 0; j < 4; j++) {
                int col = px0 + wn + j * 8 + kq * 2;
                size_t off = (size_t)row * NPIX + col;
                float v0 = fmaxf(acc[i][j][hh * 2 + 0] * inv + add, 0.f);
                float v1 = fmaxf(acc[i][j][hh * 2 + 1] * inv + add, 0.f);
                if (ROUND) { v0 = tf32r(v0); v1 = tf32r(v1); }
                *(float2*)(outp + off) = make_float2(v0, v1);
            }
        }
    }
}

// ---------------- qkv via TC (unchanged) ----------------
#define QBSTG (256 * 16)
__global__ void __launch_bounds__(256, 1) qkv_tc()
{
    __shared__ float Asm[2][64 * ASTRIDE];
    __shared__ float Bsm[2][QBSTG];

    int tid = threadIdx.x, lane = tid & 31, wid = tid >> 5;
    int wn = wid * 32;
    int px0 = blockIdx.x * 256;
    int oc0 = blockIdx.y * 64;
    int b = blockIdx.z;
    const float* in = g_out1 + (size_t)b * ICd * NPIX;
    float* outp = g_qkv + (size_t)b * 192 * NPIX;

    int arow = tid >> 1, ahalf = tid & 1;
    int px = px0 + tid;
    int rsw = (tid >> 1) & 3;

    float4 pa0, pa1;
    float pb[16];
    auto loadA = [&](int c) {
        if (tid < 128) {
            const float* ap = g_wqkv + (size_t)(oc0 + arow) * 128 + c * 16 + ahalf * 8;
            pa0 = *(const float4*)ap;
            pa1 = *(const float4*)(ap + 4);
        }
    };
    auto loadB = [&](int c) {
        const float* sp = in + (size_t)(c * 16) * NPIX + px;
#pragma unroll
        for (int k = 0; k < 16; k++)
            pb[k] = __ldg(sp + (size_t)k * NPIX);
    };
    auto storeAB = [&](int s) {
        if (tid < 128) {
            float* Ad = &Asm[s][arow * ASTRIDE + ahalf * 2];
            float av0[4] = {pa0.x, pa0.y, pa0.z, pa0.w};
            float av1[4] = {pa1.x, pa1.y, pa1.z, pa1.w};
#pragma unroll
            for (int t = 0; t < 4; t++)
                *(float2*)(Ad + t * 4) = make_float2(av0[t], av1[t]);
        }
        float* Bd = &Bsm[s][tid * 16];
#pragma unroll
        for (int t = 0; t < 4; t++)
            *(float4*)(Bd + ((t ^ rsw) * 4)) =
                make_float4(pb[t], pb[t + 4], pb[t + 8], pb[t + 12]);
    };

    float acc[4][4][4];
#pragma unroll
    for (int i = 0; i < 4; i++)
#pragma unroll
        for (int j = 0; j < 4; j++)
#pragma unroll
            for (int r = 0; r < 4; r++) acc[i][j][r] = 0.f;

    loadA(0); loadB(0); storeAB(0);
    __syncthreads();

    int kq = lane & 3, g4 = lane >> 2;
    const int NCHUNK = 8;
    for (int c = 0; c < NCHUNK; c++) {
        int s = c & 1;
        if (c + 1 < NCHUNK) { loadA(c + 1); loadB(c + 1); }
        const float* Ab = &Asm[s][0];
        const float* Bb = &Bsm[s][0];
        float4 alo[4], ahi[4], bfr[4];
#pragma unroll
        for (int i = 0; i < 4; i++) {
            int m = i * 16 + g4;
            alo[i] = *(const float4*)(Ab + m * ASTRIDE + kq * 4);
            ahi[i] = *(const float4*)(Ab + (m + 8) * ASTRIDE + kq * 4);
        }
#pragma unroll
        for (int j = 0; j < 4; j++) {
            int n = wn + j * 8 + g4;
            int slot = kq ^ ((n >> 1) & 3);
            bfr[j] = *(const float4*)(Bb + n * 16 + slot * 4);
        }
#pragma unroll
        for (int kk = 0; kk < 2; kk++) {
#pragma unroll
            for (int i = 0; i < 4; i++) {
                uint32_t af[4];
                if (kk == 0) {
                    af[0] = __float_as_uint(alo[i].x); af[1] = __float_as_uint(ahi[i].x);
                    af[2] = __float_as_uint(alo[i].y); af[3] = __float_as_uint(ahi[i].y);
                } else {
                    af[0] = __float_as_uint(alo[i].z); af[1] = __float_as_uint(ahi[i].z);
                    af[2] = __float_as_uint(alo[i].w); af[3] = __float_as_uint(ahi[i].w);
                }
#pragma unroll
                for (int j = 0; j < 4; j++) {
                    uint32_t bu[2];
                    if (kk == 0) { bu[0] = __float_as_uint(bfr[j].x); bu[1] = __float_as_uint(bfr[j].y); }
                    else         { bu[0] = __float_as_uint(bfr[j].z); bu[1] = __float_as_uint(bfr[j].w); }
                    mma1688(acc[i][j], af, bu);
                }
            }
        }
        if (c + 1 < NCHUNK) storeAB(s ^ 1);
        __syncthreads();
    }

#pragma unroll
    for (int i = 0; i < 4; i++) {
#pragma unroll
        for (int hh = 0; hh < 2; hh++) {
            int row = oc0 + i * 16 + g4 + hh * 8;
            float add = g_bqkv[row];
#pragma unroll
            for (int j = 0; j < 4; j++) {
                int col = px0 + wn + j * 8 + kq * 2;
                *(float2*)(outp + (size_t)row * NPIX + col) = make_float2(
                    acc[i][j][hh * 2 + 0] + add, acc[i][j][hh * 2 + 1] + add);
            }
        }
    }
}

// ---------------- final fused: out = W2*bott1 + b2 + att'*xr + x ----------------
__global__ void __launch_bounds__(256, 2) final_tc(
    const float* __restrict__ xexact, const float* __restrict__ b2,
    float* __restrict__ outp)
{
    extern __shared__ float dsm[];
    float* Asm = dsm;
    float* Bsm = dsm + 2 * ASTG;

    int tid = threadIdx.x, lane = tid & 31, wid = tid >> 5;
    int wm = (wid & 1) * 64, wn = (wid >> 1) * 32;
    int px0 = blockIdx.x * 128;
    int oc0 = blockIdx.y * 128;
    int b = blockIdx.z;
    const float* B1 = g_bott1 + (size_t)b * Cc * NPIX;
    const float* B2 = g_xr + (size_t)b * Cc * NPIX;
    const float* A2 = g_energy + (size_t)b * Cc * Cc;
    const float* xb = xexact + (size_t)b * Cc * NPIX;
    outp += (size_t)b * Cc * NPIX;

    int arow = tid >> 1, ahalf = tid & 1;
    int pxl = tid & 127;
    int khalf = tid >> 7;
    int px = px0 + pxl;
    int rswB = (pxl >> 1) & 3;
    int kq = lane & 3, g4 = lane >> 2;

    float4 pa0, pa1;
    float pb[8];
    auto loadA = [&](int c) {
        int p = c >> 5;
        int ic = (c & 31) * 16;
        const float* base = p ? A2 : g_w2r;
        const float* ap = base + (size_t)(oc0 + arow) * Cc + ic + ahalf * 8;
        pa0 = *(const float4*)ap;
        pa1 = *(const float4*)(ap + 4);
    };
    auto loadB = [&](int c) {
        int p = c >> 5;
        int ic = (c & 31) * 16;
        const float* sp = (p ? B2 : B1) + (size_t)ic * NPIX + px;
#pragma unroll
        for (int t2 = 0; t2 < 2; t2++) {
            int slot = khalf * 2 + t2;
#pragma unroll
            for (int u = 0; u < 4; u++)
                pb[t2 * 4 + u] = __ldg(sp + (size_t)(slot + u * 4) * NPIX);
        }
    };
    auto storeAB = [&](int sl) {
        float* Ad = Asm + sl * ASTG + arow * ASTRIDE + ahalf * 2;
        float av0[4] = {pa0.x, pa0.y, pa0.z, pa0.w};
        float av1[4] = {pa1.x, pa1.y, pa1.z, pa1.w};
#pragma unroll
        for (int t = 0; t < 4; t++)
            *(float2*)(Ad + t * 4) = make_float2(av0[t], av1[t]);
        float* Bd = Bsm + sl * BSTG + pxl * 16;
#pragma unroll
        for (int t2 = 0; t2 < 2; t2++) {
            int slot = khalf * 2 + t2;
            *(float4*)(Bd + ((slot ^ rswB) * 4)) =
                make_float4(pb[t2 * 4 + 0], pb[t2 * 4 + 1], pb[t2 * 4 + 2], pb[t2 * 4 + 3]);
        }
    };

    float acc[4][4][4];
#pragma unroll
    for (int i = 0; i < 4; i++)
#pragma unroll
        for (int j = 0; j < 4; j++)
#pragma unroll
            for (int r = 0; r < 4; r++) acc[i][j][r] = 0.f;

    auto doMMA = [&](int sl) {
        const float* Ab = Asm + sl * ASTG;
        const float* Bb = Bsm + sl * BSTG;
        float4 alo[4], ahi[4], bfr[4];
#pragma unroll
        for (int i = 0; i < 4; i++) {
            int m = wm + i * 16 + g4;
            alo[i] = *(const float4*)(Ab + m * ASTRIDE + kq * 4);
            ahi[i] = *(const float4*)(Ab + (m + 8) * ASTRIDE + kq * 4);
        }
#pragma unroll
        for (int j = 0; j < 4; j++) {
            int n = wn + j * 8 + g4;
            int slot = kq ^ ((n >> 1) & 3);
            bfr[j] = *(const float4*)(Bb + n * 16 + slot * 4);
        }
#pragma unroll
        for (int kk = 0; kk < 2; kk++) {
#pragma unroll
            for (int i = 0; i < 4; i++) {
                uint32_t af[4];
                if (kk == 0) {
                    af[0] = __float_as_uint(alo[i].x); af[1] = __float_as_uint(ahi[i].x);
                    af[2] = __float_as_uint(alo[i].y); af[3] = __float_as_uint(ahi[i].y);
                } else {
                    af[0] = __float_as_uint(alo[i].z); af[1] = __float_as_uint(ahi[i].z);
                    af[2] = __float_as_uint(alo[i].w); af[3] = __float_as_uint(ahi[i].w);
                }
#pragma unroll
                for (int j = 0; j < 4; j++) {
                    uint32_t bu[2];
                    if (kk == 0) { bu[0] = __float_as_uint(bfr[j].x); bu[1] = __float_as_uint(bfr[j].y); }
                    else         { bu[0] = __float_as_uint(bfr[j].z); bu[1] = __float_as_uint(bfr[j].w); }
                    mma1688(acc[i][j], af, bu);
                }
            }
        }
    };

    loadA(0); loadB(0); storeAB(0);
    __syncthreads();

    const int NCHUNK = 64;
    for (int c = 0; c < NCHUNK; c++) {
        int s = c & 1;
        if (c + 1 < NCHUNK) { loadA(c + 1); loadB(c + 1); }
        doMMA(s);
        if (c + 1 < NCHUNK) storeAB(s ^ 1);
        __syncthreads();
    }

#pragma unroll
    for (int i = 0; i < 4; i++) {
#pragma unroll
        for (int hh = 0; hh < 2; hh++) {
            int row = oc0 + wm + i * 16 + g4 + hh * 8;
            float add = __ldg(b2 + row);
#pragma unroll
            for (int j = 0; j < 4; j++) {
                int col = px0 + wn + j * 8 + kq * 2;
                size_t off = (size_t)row * NPIX + col;
                float2 xv = *(const float2*)(xb + off);
                *(float2*)(outp + off) = make_float2(
                    acc[i][j][hh * 2 + 0] + add + xv.x,
                    acc[i][j][hh * 2 + 1] + add + xv.y);
            }
        }
    }
}

// ---------------- CAM energy: 3xTF32 TC, split-K, on-the-fly hi/lo split ----------------
__global__ void __launch_bounds__(256, 2) egemm_tc(const float* __restrict__ xexact)
{
    __shared__ float Ah[128][20], Al[128][20], Bh[128][20], Bl[128][20];

    int bz = blockIdx.z;
    int b = bz / ESPLIT, ks = bz - b * ESPLIT;
    const float* X = xexact + (size_t)b * Cc * NPIX;
    float* Cm = g_epart + (size_t)(ks * Bq + b) * Cc * Cc;
    const int KCH = NPIX / ESPLIT;
    int k0s = ks * KCH, k0e = k0s + KCH;

    int tid = threadIdx.x, lane = tid & 31, wid = tid >> 5;
    int wm = (wid & 1) * 64, wn = (wid >> 1) * 32;
    int row0 = blockIdx.y * 128, col0 = blockIdx.x * 128;
    int ar = tid >> 1, ak = (tid & 1) * 8;
    const float* Arx = X + (size_t)(row0 + ar) * NPIX + ak;
    const float* Brx = X + (size_t)(col0 + ar) * NPIX + ak;

    float acc[4][4][4];
#pragma unroll
    for (int i = 0; i < 4; i++)
#pragma unroll
        for (int j = 0; j < 4; j++)
#pragma unroll
            for (int r = 0; r < 4; r++) acc[i][j][r] = 0.f;

    for (int k0 = k0s; k0 < k0e; k0 += 16) {
        __syncthreads();
#pragma unroll
        for (int half = 0; half < 2; half++) {
            float4 va = *(const float4*)(Arx + k0 + half * 4);
            float4 vb4 = *(const float4*)(Brx + k0 + half * 4);
            float4 h, l;
            h.x = tf32r(va.x); l.x = tf32r(va.x - h.x);
            h.y = tf32r(va.y); l.y = tf32r(va.y - h.y);
            h.z = tf32r(va.z); l.z = tf32r(va.z - h.z);
            h.w = tf32r(va.w); l.w = tf32r(va.w - h.w);
            *(float4*)&Ah[ar][ak + half * 4] = h;
            *(float4*)&Al[ar][ak + half * 4] = l;
            h.x = tf32r(vb4.x); l.x = tf32r(vb4.x - h.x);
            h.y = tf32r(vb4.y); l.y = tf32r(vb4.y - h.y);
            h.z = tf32r(vb4.z); l.z = tf32r(vb4.z - h.z);
            h.w = tf32r(vb4.w); l.w = tf32r(vb4.w - h.w);
            *(float4*)&Bh[ar][ak + half * 4] = h;
            *(float4*)&Bl[ar][ak + half * 4] = l;
        }
        __syncthreads();
#pragma unroll
        for (int kk = 0; kk < 16; kk += 8) {
            int kq = kk + (lane & 3);
            int g4 = lane >> 2;
            uint32_t ah[4][4], al[4][4];
#pragma unroll
            for (int i = 0; i < 4; i++) {
                int m = wm + i * 16 + g4;
                ah[i][0] = __float_as_uint(Ah[m][kq]);
                ah[i][1] = __float_as_uint(Ah[m + 8][kq]);
                ah[i][2] = __float_as_uint(Ah[m][kq + 4]);
                ah[i][3] = __float_as_uint(Ah[m + 8][kq + 4]);
                al[i][0] = __float_as_uint(Al[m][kq]);
                al[i][1] = __float_as_uint(Al[m + 8][kq]);
                al[i][2] = __float_as_uint(Al[m][kq + 4]);
                al[i][3] = __float_as_uint(Al[m + 8][kq + 4]);
            }
#pragma unroll
            for (int j = 0; j < 4; j++) {
                int n = wn + j * 8 + g4;
                uint32_t bh[2], bl[2];
                bh[0] = __float_as_uint(Bh[n][kq]);
                bh[1] = __float_as_uint(Bh[n][kq + 4]);
                bl[0] = __float_as_uint(Bl[n][kq]);
                bl[1] = __float_as_uint(Bl[n][kq + 4]);
#pragma unroll
                for (int i = 0; i < 4; i++) {
                    mma1688(acc[i][j], ah[i], bh);
                    mma1688(acc[i][j], ah[i], bl);
                    mma1688(acc[i][j], al[i], bh);
                }
            }
        }
    }

#pragma unroll
    for (int i = 0; i < 4; i++) {
#pragma unroll
        for (int hh = 0; hh < 2; hh++) {
            int row = row0 + wm + i * 16 + (lane >> 2) + hh * 8;
#pragma unroll
            for (int j = 0; j < 4; j++) {
                int col = col0 + wn + j * 8 + (lane & 3) * 2;
                *(float2*)&Cm[(size_t)row * Cc + col] = make_float2(
                    acc[i][j][hh * 2 + 0], acc[i][j][hh * 2 + 1]);
            }
        }
    }
}

// ---------------- criss-cross attention (barrier-free channel loop) ----------------
__global__ void __launch_bounds__(192) cca2_kernel(const float* __restrict__ gamma)
{
    extern __shared__ float sm[];
    float* e = sm;
    float* qs = sm + 192 * 96;
    float* ks_ = qs + 16 * 96;

    int h = blockIdx.x, b = blockIdx.y;
    int tid = threadIdx.x;
    const float* qb = g_qkv + (size_t)b * 192 * NPIX;
    const float* kb = qb + (size_t)16 * NPIX;
    const float* vb = qb + (size_t)32 * NPIX;

    for (int idx = tid; idx < 16 * 96; idx += 192) {
        int c = idx / 96, w = idx - c * 96;
        qs[c * 96 + w] = qb[c * NPIX + h * Wd + w];
        ks_[c * 96 + w] = kb[c * NPIX + h * Wd + w];
    }
    __syncthreads();
    for (int idx = tid; idx < 96 * 96; idx += 192) {
        int s = idx / 96, w = idx - s * 96;
        float a = 0.f;
#pragma unroll
        for (int c = 0; c < 16; c++) a += qs[c * 96 + w] * ks_[c * 96 + s];
        e[(96 + s) * 96 + w] = a;
    }
    for (int idx = tid; idx < 96 * 96; idx += 192) {
        int s = idx / 96, w = idx - s * 96;
        float a = 0.f;
#pragma unroll
        for (int c = 0; c < 16; c++) a += qs[c * 96 + w] * kb[c * NPIX + s * Wd + w];
        e[s * 96 + w] = (s == h) ? -1e30f : a;
    }
    __syncthreads();
    if (tid < 96) {
        int w = tid;
        float M = -1e30f;
        for (int i = 0; i < 192; i++) M = fmaxf(M, e[i * 96 + w]);
        float S = 0.f;
        for (int i = 0; i < 192; i++) {
            float p = __expf(e[i * 96 + w] - M);
            e[i * 96 + w] = p; S += p;
        }
        float inv = 1.f / S;
        for (int i = 0; i < 192; i++) e[i * 96 + w] *= inv;
    }
    __syncthreads();
    int g = tid / 96;
    int w = tid - g * 96;
    float gam = __ldg(gamma);
    for (int cc = 0; cc < 64; cc++) {
        int c = g * 64 + cc;
        const float* vcol = vb + (size_t)c * NPIX + w;
        const float* vrow = vb + (size_t)c * NPIX + h * 96;
        float oH = 0.f, oW = 0.f;
#pragma unroll 4
        for (int s = 0; s < 96; s++) {
            oH += vcol[s * Wd] * e[s * 96 + w];
            oW += __ldg(vrow + s) * e[(96 + s) * 96 + w];
        }
        size_t o = ((size_t)b * ICd + c) * NPIX + h * Wd + w;
        g_cca[o] = tf32r(gam * (oH + oW) + g_out1[o]);
    }
}

// ---------------- CAM softmax (sums partials, scales by gamma_cam) ----------------
__global__ void __launch_bounds__(128) cam_softmax_kernel(const float* __restrict__ gma)
{
    int b = blockIdx.y, c = blockIdx.x;
    int t = threadIdx.x;
    __shared__ float red[4];
    float4 v = make_float4(0.f, 0.f, 0.f, 0.f);
#pragma unroll
    for (int s = 0; s < ESPLIT; s++) {
        const float4 p = *(const float4*)&g_epart[(((size_t)(s * Bq + b)) * Cc + c) * Cc + t * 4];
        v.x += p.x; v.y += p.y; v.z += p.z; v.w += p.w;
    }
    float lmn = fminf(fminf(v.x, v.y), fminf(v.z, v.w));
#pragma unroll
    for (int o = 16; o; o >>= 1) lmn = fminf(lmn, __shfl_xor_sync(0xffffffffu, lmn, o));
    if ((t & 31) == 0) red[t >> 5] = lmn;
    __syncthreads();
    float mn = fminf(fminf(red[0], red[1]), fminf(red[2], red[3]));
    __syncthreads();
    float4 p;
    p.x = __expf(mn - v.x); p.y = __expf(mn - v.y);
    p.z = __expf(mn - v.z); p.w = __expf(mn - v.w);
    float ls = p.x + p.y + p.z + p.w;
#pragma unroll
    for (int o = 16; o; o >>= 1) ls += __shfl_xor_sync(0xffffffffu, ls, o);
    if ((t & 31) == 0) red[t >> 5] = ls;
    __syncthreads();
    float gam = __ldg(gma);
    float inv = gam / (red[0] + red[1] + red[2] + red[3]);
    p.x = tf32r(p.x * inv); p.y = tf32r(p.y * inv);
    p.z = tf32r(p.z * inv); p.w = tf32r(p.w * inv);
    *(float4*)&g_energy[((size_t)b * Cc + c) * Cc + t * 4] = p;
}

// ---------------- launch ----------------
extern "C" void kernel_launch(void* const* d_in, const int* in_sizes, int n_in,
                              void* d_out, int out_size)
{
    const float* x        = (const float*)d_in[0];
    const float* conva_w  = (const float*)d_in[1];
    const float* bn1_s    = (const float*)d_in[2];
    const float* bn1_b    = (const float*)d_in[3];
    const float* bn1_m    = (const float*)d_in[4];
    const float* bn1_v    = (const float*)d_in[5];
    const float* wq       = (const float*)d_in[6];
    const float* bq       = (const float*)d_in[7];
    const float* wk       = (const float*)d_in[8];
    const float* bk       = (const float*)d_in[9];
    const float* wv       = (const float*)d_in[10];
    const float* bv       = (const float*)d_in[11];
    const float* gamma_cca= (const float*)d_in[12];
    const float* convb_w  = (const float*)d_in[13];
    const float* bn2_s    = (const float*)d_in[14];
    const float* bn2_b    = (const float*)d_in[15];
    const float* bn2_m    = (const float*)d_in[16];
    const float* bn2_v    = (const float*)d_in[17];
    const float* bot_w1   = (const float*)d_in[18];
    const float* bn3_s    = (const float*)d_in[19];
    const float* bn3_b    = (const float*)d_in[20];
    const float* bn3_m    = (const float*)d_in[21];
    const float* bn3_v    = (const float*)d_in[22];
    const float* bot_w2   = (const float*)d_in[23];
    const float* bot_b2   = (const float*)d_in[24];
    const float* gamma_cam= (const float*)d_in[25];
    float* out = (float*)d_out;

    float *p_xr, *p_cca, *p_b1, *p_wta, *p_wtb, *p_wt1, *p_out1, *p_out2;
    cudaGetSymbolAddress((void**)&p_xr, g_xr);
    cudaGetSymbolAddress((void**)&p_cca, g_cca);
    cudaGetSymbolAddress((void**)&p_b1, g_bott1);
    cudaGetSymbolAddress((void**)&p_wta, g_wta);
    cudaGetSymbolAddress((void**)&p_wtb, g_wtb);
    cudaGetSymbolAddress((void**)&p_wt1, g_wt1);
    cudaGetSymbolAddress((void**)&p_out1, g_out1);
    cudaGetSymbolAddress((void**)&p_out2, g_out2);

    cudaFuncSetAttribute(cca2_kernel, cudaFuncAttributeMaxDynamicSharedMemorySize, 90112);
    cudaFuncSetAttribute(conv_tc<9, true>, cudaFuncAttributeMaxDynamicSharedMemorySize, CONV_SMEM);
    cudaFuncSetAttribute(final_tc, cudaFuncAttributeMaxDynamicSharedMemorySize, CONV_SMEM);

    // prep
    roundcopy4<<<512, 256>>>(x, p_xr, Bq * Cc * NPIX / 4);
    prep_weights<<<512, 256>>>(conva_w, convb_w, bot_w1, bot_w2,
                               wq, bq, wk, bk, wv, bv);

    // conva 512->128 (+bn1+relu, rounded)
    conv_tc<9, true><<<dim3(72, 1, Bq), 256, CONV_SMEM>>>(
        p_xr, Cc, nullptr, 0, p_wta, ICd, p_out1,
        bn1_s, bn1_b, bn1_m, bn1_v);

    // qkv via tensor cores
    qkv_tc<<<dim3(36, 3, Bq), 256>>>();

    // cca
    cca2_kernel<<<dim3(Hd, Bq), 192, 90112>>>(gamma_cca);

    // convb 128->128 (+bn2+relu, rounded)
    conv_tc<9, true><<<dim3(72, 1, Bq), 256, CONV_SMEM>>>(
        p_cca, ICd, nullptr, 0, p_wtb, ICd, p_out2,
        bn2_s, bn2_b, bn2_m, bn2_v);

    // bot conv1 concat(x,out2) 640->512 (+bn3+relu, rounded)
    conv_tc<9, true><<<dim3(72, 4, Bq), 256, CONV_SMEM>>>(
        p_xr, Cc, p_out2, ICd, p_wt1, Cc, p_b1,
        bn3_s, bn3_b, bn3_m, bn3_v);

    // CAM energy (3xTF32 TC, split-K, on-the-fly split)
    egemm_tc<<<dim3(Cc / 128, Cc / 128, Bq * ESPLIT), 256>>>(x);

    // CAM softmax -> g_energy (gamma-scaled attention)
    cam_softmax_kernel<<<dim3(Cc, Bq), 128>>>(gamma_cam);

    // final fused: out = W2*bott1 + b2 + att'*xr + x
    final_tc<<<dim3(72, 4, Bq), 256, CONV_SMEM>>>(x, bot_b2, out);
}

// round 16
// speedup vs baseline: 1.3086x; 1.3086x over previous
#include <cuda_runtime.h>
#include <cstdint>

#define Bq 4
#define Cc 512
#define NPIX 9216
#define ICd 128
#define Hd 96
#define Wd 96
#define ESPLIT 8

// ---------------- scratch ----------------
__device__ float g_xr[(size_t)Bq * Cc * NPIX];    // tf32-rounded x
__device__ float g_out1[Bq * ICd * NPIX];
__device__ float g_qkv[(size_t)Bq * 192 * NPIX];  // rows: 0-15 q, 16-31 k, 32-159 v
__device__ float g_cca[Bq * ICd * NPIX];
__device__ float g_out2[Bq * ICd * NPIX];
__device__ float g_bott1[(size_t)Bq * Cc * NPIX];
__device__ float g_energy[Bq * Cc * Cc];
__device__ float g_epart[(size_t)ESPLIT * Bq * Cc * Cc];
__device__ float g_wta[9 * 128 * 512];
__device__ float g_wtb[9 * 128 * 128];
__device__ float g_wt1[9 * 512 * 640];
__device__ float g_w2r[512 * 512];
__device__ float g_wqkv[192 * 128];
__device__ float g_bqkv[192];

__device__ __forceinline__ float tf32r(float x) {
    uint32_t u;
    asm("cvt.rna.tf32.f32 %0, %1;" : "=r"(u) : "f"(x));
    return __uint_as_float(u);
}

__device__ __forceinline__ void mma1688(float* c, const uint32_t* a, const uint32_t* b) {
    asm volatile(
        "mma.sync.aligned.m16n8k8.row.col.f32.tf32.tf32.f32 "
        "{%0,%1,%2,%3}, {%4,%5,%6,%7}, {%8,%9}, {%0,%1,%2,%3};"
        : "+f"(c[0]), "+f"(c[1]), "+f"(c[2]), "+f"(c[3])
        : "r"(a[0]), "r"(a[1]), "r"(a[2]), "r"(a[3]), "r"(b[0]), "r"(b[1]));
}

// ---------------- prep ----------------
__global__ void roundcopy4(const float* __restrict__ s, float* __restrict__ d, int n4) {
    for (int i = blockIdx.x * blockDim.x + threadIdx.x; i < n4; i += gridDim.x * blockDim.x) {
        float4 v = ((const float4*)s)[i];
        v.x = tf32r(v.x); v.y = tf32r(v.y); v.z = tf32r(v.z); v.w = tf32r(v.w);
        ((float4*)d)[i] = v;
    }
}

__global__ void prep_weights(const float* __restrict__ wa, const float* __restrict__ wb,
                             const float* __restrict__ w1, const float* __restrict__ w2,
                             const float* __restrict__ wq, const float* __restrict__ bq,
                             const float* __restrict__ wk, const float* __restrict__ bk,
                             const float* __restrict__ wv, const float* __restrict__ bv)
{
    const int n1 = 128 * 512 * 9;
    const int n2 = 128 * 128 * 9;
    const int n3 = 512 * 640 * 9;
    const int n4 = 512 * 512;
    const int n5 = 192 * 128;
    const int ntot = n1 + n2 + n3 + n4 + n5 + 192;
    for (int i = blockIdx.x * blockDim.x + threadIdx.x; i < ntot; i += gridDim.x * blockDim.x) {
        if (i < n1) {
            int oc = i / (512 * 9);
            int rem = i - oc * (512 * 9);
            int ic = rem / 9, tap = rem - ic * 9;
            g_wta[((size_t)tap * 128 + oc) * 512 + ic] = tf32r(wa[i]);
        } else if (i < n1 + n2) {
            int j = i - n1;
            int oc = j / (128 * 9);
            int rem = j - oc * (128 * 9);
            int ic = rem / 9, tap = rem - ic * 9;
            g_wtb[((size_t)tap * 128 + oc) * 128 + ic] = tf32r(wb[j]);
        } else if (i < n1 + n2 + n3) {
            int j = i - n1 - n2;
            int oc = j / (640 * 9);
            int rem = j - oc * (640 * 9);
            int ic = rem / 9, tap = rem - ic * 9;
            g_wt1[((size_t)tap * 512 + oc) * 640 + ic] = tf32r(w1[j]);
        } else if (i < n1 + n2 + n3 + n4) {
            int j = i - n1 - n2 - n3;
            g_w2r[j] = tf32r(w2[j]);
        } else if (i < n1 + n2 + n3 + n4 + n5) {
            int j = i - n1 - n2 - n3 - n4;
            int r = j >> 7, ic = j & 127;
            float v = 0.f;
            if (r < 16) v = wq[r * 128 + ic];
            else if (r < 32) v = wk[(r - 16) * 128 + ic];
            else if (r < 160) v = wv[(r - 32) * 128 + ic];
            g_wqkv[j] = tf32r(v);
        } else {
            int r = i - n1 - n2 - n3 - n4 - n5;
            float v = 0.f;
            if (r < 16) v = bq[r];
            else if (r < 32) v = bk[r - 16];
            else if (r < 160) v = bv[r - 32];
            g_bqkv[r] = v;
        }
    }
}

// ---------------- tf32 TC implicit-GEMM conv (+BN+ReLU) ----------------
// CTA: 128 oc x 256 px, 8 warps of 64x64. A perm-K (stride 20); B perm-K
// XOR-swizzled [px][16]. TWO 16-K chunks per barrier (4 slots each buffer).
#define ASTRIDE 20
#define ASTG (128 * ASTRIDE)
#define BSTG (256 * 16)
#define CONV_SMEM ((4 * ASTG + 4 * BSTG) * 4)

template<int NTAPS, bool ROUND>
__global__ void __launch_bounds__(256, 1) conv_tc(
    const float* __restrict__ in1, int cin1,
    const float* __restrict__ in2, int cin2,
    const float* __restrict__ Aw, int OCtot,
    float* __restrict__ outp,
    const float* __restrict__ q0, const float* __restrict__ q1,
    const float* __restrict__ q2, const float* __restrict__ q3)
{
    const int CIN = cin1 + cin2;
    const int NCHUNK = (NTAPS * CIN) / 16;   // always even here

    extern __shared__ float dsm[];
    float* Asm = dsm;                 // 4 slots
    float* Bsm = dsm + 4 * ASTG;      // 4 slots

    int tid = threadIdx.x, lane = tid & 31, wid = tid >> 5;
    int wm = (wid & 1) * 64, wn = (wid >> 1) * 64;
    int px0 = blockIdx.x * 256;
    int oc0 = blockIdx.y * 128;
    int b = blockIdx.z;
    in1 += (size_t)b * cin1 * NPIX;
    if (cin2 > 0) in2 += (size_t)b * cin2 * NPIX;
    outp += (size_t)b * OCtot * NPIX;

    int arow = tid >> 1, ahalf = tid & 1;
    int px = px0 + tid;
    int ph = px / 96, pw = px - ph * 96;
    int rsw = (tid >> 1) & 3;
    int kq = lane & 3, g4 = lane >> 2;

    float4 pa0, pa1;
    float pb[16];

    auto loadA = [&](int c) {
        int ko = c * 16;
        int tap = (NTAPS == 9) ? ko / CIN : 0;
        int ic = ko - tap * CIN;
        const float* ap = Aw + ((size_t)tap * OCtot + oc0 + arow) * CIN + ic + ahalf * 8;
        pa0 = *(const float4*)ap;
        pa1 = *(const float4*)(ap + 4);
    };
    auto loadB = [&](int c) {
        int ko = c * 16;
        int tap = (NTAPS == 9) ? ko / CIN : 0;
        int ic = ko - tap * CIN;
        const float* src = (ic < cin1) ? (in1 + (size_t)ic * NPIX)
                                       : (in2 + (size_t)(ic - cin1) * NPIX);
        if (NTAPS == 9) {
            int dh = tap / 3 - 1, dw = tap % 3 - 1;
            int hh = ph + dh, ww = pw + dw;
            bool ok = ((unsigned)hh < 96u) && ((unsigned)ww < 96u);
            const float* sp = src + px + dh * 96 + dw;
#pragma unroll
            for (int k = 0; k < 16; k++)
                pb[k] = ok ? __ldg(sp + (size_t)k * NPIX) : 0.f;
        } else {
#pragma unroll
            for (int k = 0; k < 16; k++)
                pb[k] = __ldg(src + (size_t)k * NPIX + px);
        }
    };
    auto storeAB = [&](int sl) {
        float* Ad = Asm + sl * ASTG + arow * ASTRIDE + ahalf * 2;
        float av0[4] = {pa0.x, pa0.y, pa0.z, pa0.w};
        float av1[4] = {pa1.x, pa1.y, pa1.z, pa1.w};
#pragma unroll
        for (int t = 0; t < 4; t++)
            *(float2*)(Ad + t * 4) = make_float2(av0[t], av1[t]);
        float* Bd = Bsm + sl * BSTG + tid * 16;
#pragma unroll
        for (int t = 0; t < 4; t++)
            *(float4*)(Bd + ((t ^ rsw) * 4)) =
                make_float4(pb[t], pb[t + 4], pb[t + 8], pb[t + 12]);
    };

    float acc[4][8][4];
#pragma unroll
    for (int i = 0; i < 4; i++)
#pragma unroll
        for (int j = 0; j < 8; j++)
#pragma unroll
            for (int r = 0; r < 4; r++) acc[i][j][r] = 0.f;

    auto doMMA = [&](int sl) {
        const float* Ab = Asm + sl * ASTG;
        const float* Bb = Bsm + sl * BSTG;
        float4 alo[4], ahi[4], bfr[8];
#pragma unroll
        for (int i = 0; i < 4; i++) {
            int m = wm + i * 16 + g4;
            alo[i] = *(const float4*)(Ab + m * ASTRIDE + kq * 4);
            ahi[i] = *(const float4*)(Ab + (m + 8) * ASTRIDE + kq * 4);
        }
#pragma unroll
        for (int j = 0; j < 8; j++) {
            int n = wn + j * 8 + g4;
            int slot = kq ^ ((n >> 1) & 3);
            bfr[j] = *(const float4*)(Bb + n * 16 + slot * 4);
        }
#pragma unroll
        for (int kk = 0; kk < 2; kk++) {
#pragma unroll
            for (int i = 0; i < 4; i++) {
                uint32_t af[4];
                if (kk == 0) {
                    af[0] = __float_as_uint(alo[i].x); af[1] = __float_as_uint(ahi[i].x);
                    af[2] = __float_as_uint(alo[i].y); af[3] = __float_as_uint(ahi[i].y);
                } else {
                    af[0] = __float_as_uint(alo[i].z); af[1] = __float_as_uint(ahi[i].z);
                    af[2] = __float_as_uint(alo[i].w); af[3] = __float_as_uint(ahi[i].w);
                }
#pragma unroll
                for (int j = 0; j < 8; j++) {
                    uint32_t bu[2];
                    if (kk == 0) { bu[0] = __float_as_uint(bfr[j].x); bu[1] = __float_as_uint(bfr[j].y); }
                    else         { bu[0] = __float_as_uint(bfr[j].z); bu[1] = __float_as_uint(bfr[j].w); }
                    mma1688(acc[i][j], af, bu);
                }
            }
        }
    };

    // prologue: fill slots 0,1 (stage 0)
    loadB(0); loadA(0); storeAB(0);
    loadB(1); loadA(1); storeAB(1);
    __syncthreads();

    for (int cc = 0; cc < NCHUNK; cc += 2) {
        int st = (cc >> 1) & 1;
        bool more = (cc + 2 < NCHUNK);
        // chunk cc
        if (more) { loadB(cc + 2); loadA(cc + 2); }
        doMMA(st * 2 + 0);
        if (more) storeAB((st ^ 1) * 2 + 0);
        // chunk cc+1
        if (more) { loadB(cc + 3); loadA(cc + 3); }
        doMMA(st * 2 + 1);
        if (more) storeAB((st ^ 1) * 2 + 1);
        __syncthreads();
    }

#pragma unroll
    for (int i = 0; i < 4; i++) {
#pragma unroll
        for (int hh = 0; hh < 2; hh++) {
            int row = oc0 + wm + i * 16 + g4 + hh * 8;
            float inv = __ldg(q0 + row) * rsqrtf(__ldg(q3 + row) + 1e-5f);
            float add = __ldg(q1 + row) - __ldg(q2 + row) * inv;
#pragma unroll
            for (int j = 0; j < 8; j++) {
                int col = px0 + wn + j * 8 + kq * 2;
                size_t off = (size_t)row * NPIX + col;
                float v0 = fmaxf(acc[i][j][hh * 2 + 0] * inv + add, 0.f);
                float v1 = fmaxf(acc[i][j][hh * 2 + 1] * inv + add, 0.f);
                if (ROUND) { v0 = tf32r(v0); v1 = tf32r(v1); }
                *(float2*)(outp + off) = make_float2(v0, v1);
            }
        }
    }
}

// ---------------- qkv via TC (unchanged) ----------------
__global__ void __launch_bounds__(256, 1) qkv_tc()
{
    __shared__ float Asm[2][64 * ASTRIDE];
    __shared__ float Bsm[2][BSTG];

    int tid = threadIdx.x, lane = tid & 31, wid = tid >> 5;
    int wn = wid * 32;
    int px0 = blockIdx.x * 256;
    int oc0 = blockIdx.y * 64;
    int b = blockIdx.z;
    const float* in = g_out1 + (size_t)b * ICd * NPIX;
    float* outp = g_qkv + (size_t)b * 192 * NPIX;

    int arow = tid >> 1, ahalf = tid & 1;
    int px = px0 + tid;
    int rsw = (tid >> 1) & 3;

    float4 pa0, pa1;
    float pb[16];
    auto loadA = [&](int c) {
        if (tid < 128) {
            const float* ap = g_wqkv + (size_t)(oc0 + arow) * 128 + c * 16 + ahalf * 8;
            pa0 = *(const float4*)ap;
            pa1 = *(const float4*)(ap + 4);
        }
    };
    auto loadB = [&](int c) {
        const float* sp = in + (size_t)(c * 16) * NPIX + px;
#pragma unroll
        for (int k = 0; k < 16; k++)
            pb[k] = __ldg(sp + (size_t)k * NPIX);
    };
    auto storeAB = [&](int s) {
        if (tid < 128) {
            float* Ad = &Asm[s][arow * ASTRIDE + ahalf * 2];
            float av0[4] = {pa0.x, pa0.y, pa0.z, pa0.w};
            float av1[4] = {pa1.x, pa1.y, pa1.z, pa1.w};
#pragma unroll
            for (int t = 0; t < 4; t++)
                *(float2*)(Ad + t * 4) = make_float2(av0[t], av1[t]);
        }
        float* Bd = &Bsm[s][tid * 16];
#pragma unroll
        for (int t = 0; t < 4; t++)
            *(float4*)(Bd + ((t ^ rsw) * 4)) =
                make_float4(pb[t], pb[t + 4], pb[t + 8], pb[t + 12]);
    };

    float acc[4][4][4];
#pragma unroll
    for (int i = 0; i < 4; i++)
#pragma unroll
        for (int j = 0; j < 4; j++)
#pragma unroll
            for (int r = 0; r < 4; r++) acc[i][j][r] = 0.f;

    loadA(0); loadB(0); storeAB(0);
    __syncthreads();

    int kq = lane & 3, g4 = lane >> 2;
    const int NCHUNK = 8;
    for (int c = 0; c < NCHUNK; c++) {
        int s = c & 1;
        if (c + 1 < NCHUNK) { loadA(c + 1); loadB(c + 1); }
        const float* Ab = &Asm[s][0];
        const float* Bb = &Bsm[s][0];
        float4 alo[4], ahi[4], bfr[4];
#pragma unroll
        for (int i = 0; i < 4; i++) {
            int m = i * 16 + g4;
            alo[i] = *(const float4*)(Ab + m * ASTRIDE + kq * 4);
            ahi[i] = *(const float4*)(Ab + (m + 8) * ASTRIDE + kq * 4);
        }
#pragma unroll
        for (int j = 0; j < 4; j++) {
            int n = wn + j * 8 + g4;
            int slot = kq ^ ((n >> 1) & 3);
            bfr[j] = *(const float4*)(Bb + n * 16 + slot * 4);
        }
#pragma unroll
        for (int kk = 0; kk < 2; kk++) {
#pragma unroll
            for (int i = 0; i < 4; i++) {
                uint32_t af[4];
                if (kk == 0) {
                    af[0] = __float_as_uint(alo[i].x); af[1] = __float_as_uint(ahi[i].x);
                    af[2] = __float_as_uint(alo[i].y); af[3] = __float_as_uint(ahi[i].y);
                } else {
                    af[0] = __float_as_uint(alo[i].z); af[1] = __float_as_uint(ahi[i].z);
                    af[2] = __float_as_uint(alo[i].w); af[3] = __float_as_uint(ahi[i].w);
                }
#pragma unroll
                for (int j = 0; j < 4; j++) {
                    uint32_t bu[2];
                    if (kk == 0) { bu[0] = __float_as_uint(bfr[j].x); bu[1] = __float_as_uint(bfr[j].y); }
                    else         { bu[0] = __float_as_uint(bfr[j].z); bu[1] = __float_as_uint(bfr[j].w); }
                    mma1688(acc[i][j], af, bu);
                }
            }
        }
        if (c + 1 < NCHUNK) storeAB(s ^ 1);
        __syncthreads();
    }

#pragma unroll
    for (int i = 0; i < 4; i++) {
#pragma unroll
        for (int hh = 0; hh < 2; hh++) {
            int row = oc0 + i * 16 + g4 + hh * 8;
            float add = g_bqkv[row];
#pragma unroll
            for (int j = 0; j < 4; j++) {
                int col = px0 + wn + j * 8 + kq * 2;
                *(float2*)(outp + (size_t)row * NPIX + col) = make_float2(
                    acc[i][j][hh * 2 + 0] + add, acc[i][j][hh * 2 + 1] + add);
            }
        }
    }
}

// ---------------- final fused: out = W2*bott1 + b2 + att'*xr + x ----------------
__global__ void __launch_bounds__(256, 1) final_tc(
    const float* __restrict__ xexact, const float* __restrict__ b2,
    float* __restrict__ outp)
{
    extern __shared__ float dsm[];
    float* Asm = dsm;
    float* Bsm = dsm + 4 * ASTG;

    int tid = threadIdx.x, lane = tid & 31, wid = tid >> 5;
    int wm = (wid & 1) * 64, wn = (wid >> 1) * 64;
    int px0 = blockIdx.x * 256;
    int oc0 = blockIdx.y * 128;
    int b = blockIdx.z;
    const float* B1 = g_bott1 + (size_t)b * Cc * NPIX;
    const float* B2 = g_xr + (size_t)b * Cc * NPIX;
    const float* A2 = g_energy + (size_t)b * Cc * Cc;
    const float* xb = xexact + (size_t)b * Cc * NPIX;
    outp += (size_t)b * Cc * NPIX;

    int arow = tid >> 1, ahalf = tid & 1;
    int px = px0 + tid;
    int rsw = (tid >> 1) & 3;
    int kq = lane & 3, g4 = lane >> 2;

    float4 pa0, pa1;
    float pb[16];
    auto loadA = [&](int c) {
        int p = c >> 5;
        int ic = (c & 31) * 16;
        const float* base = p ? A2 : g_w2r;
        const float* ap = base + (size_t)(oc0 + arow) * Cc + ic + ahalf * 8;
        pa0 = *(const float4*)ap;
        pa1 = *(const float4*)(ap + 4);
    };
    auto loadB = [&](int c) {
        int p = c >> 5;
        int ic = (c & 31) * 16;
        const float* sp = (p ? B2 : B1) + (size_t)ic * NPIX + px;
#pragma unroll
        for (int k = 0; k < 16; k++)
            pb[k] = __ldg(sp + (size_t)k * NPIX);
    };
    auto storeAB = [&](int sl) {
        float* Ad = Asm + sl * ASTG + arow * ASTRIDE + ahalf * 2;
        float av0[4] = {pa0.x, pa0.y, pa0.z, pa0.w};
        float av1[4] = {pa1.x, pa1.y, pa1.z, pa1.w};
#pragma unroll
        for (int t = 0; t < 4; t++)
            *(float2*)(Ad + t * 4) = make_float2(av0[t], av1[t]);
        float* Bd = Bsm + sl * BSTG + tid * 16;
#pragma unroll
        for (int t = 0; t < 4; t++)
            *(float4*)(Bd + ((t ^ rsw) * 4)) =
                make_float4(pb[t], pb[t + 4], pb[t + 8], pb[t + 12]);
    };

    float acc[4][8][4];
#pragma unroll
    for (int i = 0; i < 4; i++)
#pragma unroll
        for (int j = 0; j < 8; j++)
#pragma unroll
            for (int r = 0; r < 4; r++) acc[i][j][r] = 0.f;

    auto doMMA = [&](int sl) {
        const float* Ab = Asm + sl * ASTG;
        const float* Bb = Bsm + sl * BSTG;
        float4 alo[4], ahi[4], bfr[8];
#pragma unroll
        for (int i = 0; i < 4; i++) {
            int m = wm + i * 16 + g4;
            alo[i] = *(const float4*)(Ab + m * ASTRIDE + kq * 4);
            ahi[i] = *(const float4*)(Ab + (m + 8) * ASTRIDE + kq * 4);
        }
#pragma unroll
        for (int j = 0; j < 8; j++) {
            int n = wn + j * 8 + g4;
            int slot = kq ^ ((n >> 1) & 3);
            bfr[j] = *(const float4*)(Bb + n * 16 + slot * 4);
        }
#pragma unroll
        for (int kk = 0; kk < 2; kk++) {
#pragma unroll
            for (int i = 0; i < 4; i++) {
                uint32_t af[4];
                if (kk == 0) {
                    af[0] = __float_as_uint(alo[i].x); af[1] = __float_as_uint(ahi[i].x);
                    af[2] = __float_as_uint(alo[i].y); af[3] = __float_as_uint(ahi[i].y);
                } else {
                    af[0] = __float_as_uint(alo[i].z); af[1] = __float_as_uint(ahi[i].z);
                    af[2] = __float_as_uint(alo[i].w); af[3] = __float_as_uint(ahi[i].w);
                }
#pragma unroll
                for (int j = 0; j < 8; j++) {
                    uint32_t bu[2];
                    if (kk == 0) { bu[0] = __float_as_uint(bfr[j].x); bu[1] = __float_as_uint(bfr[j].y); }
                    else         { bu[0] = __float_as_uint(bfr[j].z); bu[1] = __float_as_uint(bfr[j].w); }
                    mma1688(acc[i][j], af, bu);
                }
            }
        }
    };

    loadB(0); loadA(0); storeAB(0);
    loadB(1); loadA(1); storeAB(1);
    __syncthreads();

    const int NCHUNK = 64;
    for (int cc = 0; cc < NCHUNK; cc += 2) {
        int st = (cc >> 1) & 1;
        bool more = (cc + 2 < NCHUNK);
        if (more) { loadB(cc + 2); loadA(cc + 2); }
        doMMA(st * 2 + 0);
        if (more) storeAB((st ^ 1) * 2 + 0);
        if (more) { loadB(cc + 3); loadA(cc + 3); }
        doMMA(st * 2 + 1);
        if (more) storeAB((st ^ 1) * 2 + 1);
        __syncthreads();
    }

#pragma unroll
    for (int i = 0; i < 4; i++) {
#pragma unroll
        for (int hh = 0; hh < 2; hh++) {
            int row = oc0 + wm + i * 16 + g4 + hh * 8;
            float add = __ldg(b2 + row);
#pragma unroll
            for (int j = 0; j < 8; j++) {
                int col = px0 + wn + j * 8 + kq * 2;
                size_t off = (size_t)row * NPIX + col;
                float2 xv = *(const float2*)(xb + off);
                *(float2*)(outp + off) = make_float2(
                    acc[i][j][hh * 2 + 0] + add + xv.x,
                    acc[i][j][hh * 2 + 1] + add + xv.y);
            }
        }
    }
}

// ---------------- CAM energy: 3xTF32 TC, symmetric upper-tri blocks, split-K ----------------
// grid.x = 10 upper-triangular (by,bx) pairs of the 4x4 block grid; z = Bq*ESPLIT.
__global__ void __launch_bounds__(256, 2) egemm_tc(const float* __restrict__ xexact)
{
    __shared__ float Ah[128][20], Al[128][20], Bh[128][20], Bl[128][20];

    int bz = blockIdx.z;
    int b = bz / ESPLIT, ks = bz - b * ESPLIT;
    const float* X = xexact + (size_t)b * Cc * NPIX;
    float* Cm = g_epart + (size_t)(ks * Bq + b) * Cc * Cc;
    const int KCH = NPIX / ESPLIT;      // 1152
    int k0s = ks * KCH, k0e = k0s + KCH;

    // pid -> (by, bx) upper-triangular mapping
    int pid = blockIdx.x;
    int by = (pid >= 4) + (pid >= 7) + (pid >= 9);
    int base = (by == 0) ? 0 : (by == 1) ? 4 : (by == 2) ? 7 : 9;
    int bx = by + pid - base;

    int tid = threadIdx.x, lane = tid & 31, wid = tid >> 5;
    int wm = (wid & 1) * 64, wn = (wid >> 1) * 32;
    int row0 = by * 128, col0 = bx * 128;
    int ar = tid >> 1, ak = (tid & 1) * 8;
    const float* Arx = X + (size_t)(row0 + ar) * NPIX + ak;
    const float* Brx = X + (size_t)(col0 + ar) * NPIX + ak;

    float acc[4][4][4];
#pragma unroll
    for (int i = 0; i < 4; i++)
#pragma unroll
        for (int j = 0; j < 4; j++)
#pragma unroll
            for (int r = 0; r < 4; r++) acc[i][j][r] = 0.f;

    for (int k0 = k0s; k0 < k0e; k0 += 16) {
        __syncthreads();
#pragma unroll
        for (int half = 0; half < 2; half++) {
            float4 va = *(const float4*)(Arx + k0 + half * 4);
            float4 vb4 = *(const float4*)(Brx + k0 + half * 4);
            float4 h, l;
            h.x = tf32r(va.x); l.x = tf32r(va.x - h.x);
            h.y = tf32r(va.y); l.y = tf32r(va.y - h.y);
            h.z = tf32r(va.z); l.z = tf32r(va.z - h.z);
            h.w = tf32r(va.w); l.w = tf32r(va.w - h.w);
            *(float4*)&Ah[ar][ak + half * 4] = h;
            *(float4*)&Al[ar][ak + half * 4] = l;
            h.x = tf32r(vb4.x); l.x = tf32r(vb4.x - h.x);
            h.y = tf32r(vb4.y); l.y = tf32r(vb4.y - h.y);
            h.z = tf32r(vb4.z); l.z = tf32r(vb4.z - h.z);
            h.w = tf32r(vb4.w); l.w = tf32r(vb4.w - h.w);
            *(float4*)&Bh[ar][ak + half * 4] = h;
            *(float4*)&Bl[ar][ak + half * 4] = l;
        }
        __syncthreads();
#pragma unroll
        for (int kk = 0; kk < 16; kk += 8) {
            int kq = kk + (lane & 3);
            int g4 = lane >> 2;
            uint32_t ah[4][4], al[4][4];
#pragma unroll
            for (int i = 0; i < 4; i++) {
                int m = wm + i * 16 + g4;
                ah[i][0] = __float_as_uint(Ah[m][kq]);
                ah[i][1] = __float_as_uint(Ah[m + 8][kq]);
                ah[i][2] = __float_as_uint(Ah[m][kq + 4]);
                ah[i][3] = __float_as_uint(Ah[m + 8][kq + 4]);
                al[i][0] = __float_as_uint(Al[m][kq]);
                al[i][1] = __float_as_uint(Al[m + 8][kq]);
                al[i][2] = __float_as_uint(Al[m][kq + 4]);
                al[i][3] = __float_as_uint(Al[m + 8][kq + 4]);
            }
#pragma unroll
            for (int j = 0; j < 4; j++) {
                int n = wn + j * 8 + g4;
                uint32_t bh[2], bl[2];
                bh[0] = __float_as_uint(Bh[n][kq]);
                bh[1] = __float_as_uint(Bh[n][kq + 4]);
                bl[0] = __float_as_uint(Bl[n][kq]);
                bl[1] = __float_as_uint(Bl[n][kq + 4]);
#pragma unroll
                for (int i = 0; i < 4; i++) {
                    mma1688(acc[i][j], ah[i], bh);
                    mma1688(acc[i][j], ah[i], bl);
                    mma1688(acc[i][j], al[i], bh);
                }
            }
        }
    }

#pragma unroll
    for (int i = 0; i < 4; i++) {
#pragma unroll
        for (int hh = 0; hh < 2; hh++) {
            int row = row0 + wm + i * 16 + (lane >> 2) + hh * 8;
#pragma unroll
            for (int j = 0; j < 4; j++) {
                int col = col0 + wn + j * 8 + (lane & 3) * 2;
                *(float2*)&Cm[(size_t)row * Cc + col] = make_float2(
                    acc[i][j][hh * 2 + 0], acc[i][j][hh * 2 + 1]);
            }
        }
    }
}

// ---------------- criss-cross attention (barrier-free channel loop) ----------------
__global__ void __launch_bounds__(192) cca2_kernel(const float* __restrict__ gamma)
{
    extern __shared__ float sm[];
    float* e = sm;
    float* qs = sm + 192 * 96;
    float* ks_ = qs + 16 * 96;

    int h = blockIdx.x, b = blockIdx.y;
    int tid = threadIdx.x;
    const float* qb = g_qkv + (size_t)b * 192 * NPIX;
    const float* kb = qb + (size_t)16 * NPIX;
    const float* vb = qb + (size_t)32 * NPIX;

    for (int idx = tid; idx < 16 * 96; idx += 192) {
        int c = idx / 96, w = idx - c * 96;
        qs[c * 96 + w] = qb[c * NPIX + h * Wd + w];
        ks_[c * 96 + w] = kb[c * NPIX + h * Wd + w];
    }
    __syncthreads();
    for (int idx = tid; idx < 96 * 96; idx += 192) {
        int s = idx / 96, w = idx - s * 96;
        float a = 0.f;
#pragma unroll
        for (int c = 0; c < 16; c++) a += qs[c * 96 + w] * ks_[c * 96 + s];
        e[(96 + s) * 96 + w] = a;
    }
    for (int idx = tid; idx < 96 * 96; idx += 192) {
        int s = idx / 96, w = idx - s * 96;
        float a = 0.f;
#pragma unroll
        for (int c = 0; c < 16; c++) a += qs[c * 96 + w] * kb[c * NPIX + s * Wd + w];
        e[s * 96 + w] = (s == h) ? -1e30f : a;
    }
    __syncthreads();
    if (tid < 96) {
        int w = tid;
        float M = -1e30f;
        for (int i = 0; i < 192; i++) M = fmaxf(M, e[i * 96 + w]);
        float S = 0.f;
        for (int i = 0; i < 192; i++) {
            float p = __expf(e[i * 96 + w] - M);
            e[i * 96 + w] = p; S += p;
        }
        float inv = 1.f / S;
        for (int i = 0; i < 192; i++) e[i * 96 + w] *= inv;
    }
    __syncthreads();
    int g = tid / 96;
    int w = tid - g * 96;
    float gam = __ldg(gamma);
    for (int cc = 0; cc < 64; cc++) {
        int c = g * 64 + cc;
        const float* vcol = vb + (size_t)c * NPIX + w;
        const float* vrow = vb + (size_t)c * NPIX + h * 96;
        float oH = 0.f, oW = 0.f;
#pragma unroll 4
        for (int s = 0; s < 96; s++) {
            oH += vcol[s * Wd] * e[s * 96 + w];
            oW += __ldg(vrow + s) * e[(96 + s) * 96 + w];
        }
        size_t o = ((size_t)b * ICd + c) * NPIX + h * Wd + w;
        g_cca[o] = tf32r(gam * (oH + oW) + g_out1[o]);
    }
}

// ---------------- CAM softmax (sums partials incl. transposed lower blocks) ----------------
__global__ void __launch_bounds__(128) cam_softmax_kernel(const float* __restrict__ gma)
{
    int b = blockIdx.y, c = blockIdx.x;
    int t = threadIdx.x;
    __shared__ float red[4];

    int br = c >> 7;           // row block
    int bc = t >> 5;           // column block of cols t*4..t*4+3

    float4 v = make_float4(0.f, 0.f, 0.f, 0.f);
    if (bc >= br) {
#pragma unroll
        for (int s = 0; s < ESPLIT; s++) {
            const float4 p = *(const float4*)&g_epart[(((size_t)(s * Bq + b)) * Cc + c) * Cc + t * 4];
            v.x += p.x; v.y += p.y; v.z += p.z; v.w += p.w;
        }
    } else {
        // lower-triangle block: read transposed element E[col][c]
#pragma unroll
        for (int s = 0; s < ESPLIT; s++) {
            const float* basep = g_epart + ((size_t)(s * Bq + b)) * Cc * Cc;
            v.x += basep[(size_t)(t * 4 + 0) * Cc + c];
            v.y += basep[(size_t)(t * 4 + 1) * Cc + c];
            v.z += basep[(size_t)(t * 4 + 2) * Cc + c];
            v.w += basep[(size_t)(t * 4 + 3) * Cc + c];
        }
    }

    float lmn = fminf(fminf(v.x, v.y), fminf(v.z, v.w));
#pragma unroll
    for (int o = 16; o; o >>= 1) lmn = fminf(lmn, __shfl_xor_sync(0xffffffffu, lmn, o));
    if ((t & 31) == 0) red[t >> 5] = lmn;
    __syncthreads();
    float mn = fminf(fminf(red[0], red[1]), fminf(red[2], red[3]));
    __syncthreads();
    float4 p;
    p.x = __expf(mn - v.x); p.y = __expf(mn - v.y);
    p.z = __expf(mn - v.z); p.w = __expf(mn - v.w);
    float ls = p.x + p.y + p.z + p.w;
#pragma unroll
    for (int o = 16; o; o >>= 1) ls += __shfl_xor_sync(0xffffffffu, ls, o);
    if ((t & 31) == 0) red[t >> 5] = ls;
    __syncthreads();
    float gam = __ldg(gma);
    float inv = gam / (red[0] + red[1] + red[2] + red[3]);
    p.x = tf32r(p.x * inv); p.y = tf32r(p.y * inv);
    p.z = tf32r(p.z * inv); p.w = tf32r(p.w * inv);
    *(float4*)&g_energy[((size_t)b * Cc + c) * Cc + t * 4] = p;
}

// ---------------- launch ----------------
extern "C" void kernel_launch(void* const* d_in, const int* in_sizes, int n_in,
                              void* d_out, int out_size)
{
    const float* x        = (const float*)d_in[0];
    const float* conva_w  = (const float*)d_in[1];
    const float* bn1_s    = (const float*)d_in[2];
    const float* bn1_b    = (const float*)d_in[3];
    const float* bn1_m    = (const float*)d_in[4];
    const float* bn1_v    = (const float*)d_in[5];
    const float* wq       = (const float*)d_in[6];
    const float* bq       = (const float*)d_in[7];
    const float* wk       = (const float*)d_in[8];
    const float* bk       = (const float*)d_in[9];
    const float* wv       = (const float*)d_in[10];
    const float* bv       = (const float*)d_in[11];
    const float* gamma_cca= (const float*)d_in[12];
    const float* convb_w  = (const float*)d_in[13];
    const float* bn2_s    = (const float*)d_in[14];
    const float* bn2_b    = (const float*)d_in[15];
    const float* bn2_m    = (const float*)d_in[16];
    const float* bn2_v    = (const float*)d_in[17];
    const float* bot_w1   = (const float*)d_in[18];
    const float* bn3_s    = (const float*)d_in[19];
    const float* bn3_b    = (const float*)d_in[20];
    const float* bn3_m    = (const float*)d_in[21];
    const float* bn3_v    = (const float*)d_in[22];
    const float* bot_w2   = (const float*)d_in[23];
    const float* bot_b2   = (const float*)d_in[24];
    const float* gamma_cam= (const float*)d_in[25];
    float* out = (float*)d_out;

    float *p_xr, *p_cca, *p_b1, *p_wta, *p_wtb, *p_wt1, *p_out1, *p_out2;
    cudaGetSymbolAddress((void**)&p_xr, g_xr);
    cudaGetSymbolAddress((void**)&p_cca, g_cca);
    cudaGetSymbolAddress((void**)&p_b1, g_bott1);
    cudaGetSymbolAddress((void**)&p_wta, g_wta);
    cudaGetSymbolAddress((void**)&p_wtb, g_wtb);
    cudaGetSymbolAddress((void**)&p_wt1, g_wt1);
    cudaGetSymbolAddress((void**)&p_out1, g_out1);
    cudaGetSymbolAddress((void**)&p_out2, g_out2);

    cudaFuncSetAttribute(cca2_kernel, cudaFuncAttributeMaxDynamicSharedMemorySize, 90112);
    cudaFuncSetAttribute(conv_tc<9, true>, cudaFuncAttributeMaxDynamicSharedMemorySize, CONV_SMEM);
    cudaFuncSetAttribute(final_tc, cudaFuncAttributeMaxDynamicSharedMemorySize, CONV_SMEM);

    // prep
    roundcopy4<<<512, 256>>>(x, p_xr, Bq * Cc * NPIX / 4);
    prep_weights<<<512, 256>>>(conva_w, convb_w, bot_w1, bot_w2,
                               wq, bq, wk, bk, wv, bv);

    // conva 512->128 (+bn1+relu, rounded)
    conv_tc<9, true><<<dim3(36, 1, Bq), 256, CONV_SMEM>>>(
        p_xr, Cc, nullptr, 0, p_wta, ICd, p_out1,
        bn1_s, bn1_b, bn1_m, bn1_v);

    // qkv via tensor cores
    qkv_tc<<<dim3(36, 3, Bq), 256>>>();

    // cca
    cca2_kernel<<<dim3(Hd, Bq), 192, 90112>>>(gamma_cca);

    // convb 128->128 (+bn2+relu, rounded)
    conv_tc<9, true><<<dim3(36, 1, Bq), 256, CONV_SMEM>>>(
        p_cca, ICd, nullptr, 0, p_wtb, ICd, p_out2,
        bn2_s, bn2_b, bn2_m, bn2_v);

    // bot conv1 concat(x,out2) 640->512 (+bn3+relu, rounded)
    conv_tc<9, true><<<dim3(36, 4, Bq), 256, CONV_SMEM>>>(
        p_xr, Cc, p_out2, ICd, p_wt1, Cc, p_b1,
        bn3_s, bn3_b, bn3_m, bn3_v);

    // CAM energy (3xTF32 TC, symmetric upper-triangular blocks, split-K=8)
    egemm_tc<<<dim3(10, 1, Bq * ESPLIT), 256>>>(x);

    // CAM softmax -> g_energy (gamma-scaled attention, transposed lower reads)
    cam_softmax_kernel<<<dim3(Cc, Bq), 128>>>(gamma_cam);

    // final fused: out = W2*bott1 + b2 + att'*xr + x
    final_tc<<<dim3(36, 4, Bq), 256, CONV_SMEM>>>(x, bot_b2, out);
}

// round 17
// speedup vs baseline: 1.3257x; 1.0131x over previous
#include <cuda_runtime.h>
#include <cstdint>

#define Bq 4
#define Cc 512
#define NPIX 9216
#define ICd 128
#define Hd 96
#define Wd 96
#define ESPLIT 8

// ---------------- scratch ----------------
__device__ float g_xr[(size_t)Bq * Cc * NPIX];    // tf32-rounded x
__device__ float g_out1[Bq * ICd * NPIX];
__device__ float g_qkv[(size_t)Bq * 192 * NPIX];  // rows: 0-15 q, 16-31 k, 32-159 v
__device__ float g_cca[Bq * ICd * NPIX];
__device__ float g_out2[Bq * ICd * NPIX];
__device__ float g_bott1[(size_t)Bq * Cc * NPIX];
__device__ float g_energy[Bq * Cc * Cc];
__device__ float g_epart[(size_t)ESPLIT * Bq * Cc * Cc];
__device__ float g_wta[9 * 128 * 512];
__device__ float g_wtb[9 * 128 * 128];
__device__ float g_wt1[9 * 512 * 640];
__device__ float g_w2r[512 * 512];
__device__ float g_wqkv[192 * 128];
__device__ float g_bqkv[192];

__device__ __forceinline__ float tf32r(float x) {
    uint32_t u;
    asm("cvt.rna.tf32.f32 %0, %1;" : "=r"(u) : "f"(x));
    return __uint_as_float(u);
}

__device__ __forceinline__ void mma1688(float* c, const uint32_t* a, const uint32_t* b) {
    asm volatile(
        "mma.sync.aligned.m16n8k8.row.col.f32.tf32.tf32.f32 "
        "{%0,%1,%2,%3}, {%4,%5,%6,%7}, {%8,%9}, {%0,%1,%2,%3};"
        : "+f"(c[0]), "+f"(c[1]), "+f"(c[2]), "+f"(c[3])
        : "r"(a[0]), "r"(a[1]), "r"(a[2]), "r"(a[3]), "r"(b[0]), "r"(b[1]));
}

// ---------------- prep ----------------
__global__ void roundcopy4(const float* __restrict__ s, float* __restrict__ d, int n4) {
    for (int i = blockIdx.x * blockDim.x + threadIdx.x; i < n4; i += gridDim.x * blockDim.x) {
        float4 v = ((const float4*)s)[i];
        v.x = tf32r(v.x); v.y = tf32r(v.y); v.z = tf32r(v.z); v.w = tf32r(v.w);
        ((float4*)d)[i] = v;
    }
}

__global__ void prep_weights(const float* __restrict__ wa, const float* __restrict__ wb,
                             const float* __restrict__ w1, const float* __restrict__ w2,
                             const float* __restrict__ wq, const float* __restrict__ bq,
                             const float* __restrict__ wk, const float* __restrict__ bk,
                             const float* __restrict__ wv, const float* __restrict__ bv)
{
    const int n1 = 128 * 512 * 9;
    const int n2 = 128 * 128 * 9;
    const int n3 = 512 * 640 * 9;
    const int n4 = 512 * 512;
    const int n5 = 192 * 128;
    const int ntot = n1 + n2 + n3 + n4 + n5 + 192;
    for (int i = blockIdx.x * blockDim.x + threadIdx.x; i < ntot; i += gridDim.x * blockDim.x) {
        if (i < n1) {
            int oc = i / (512 * 9);
            int rem = i - oc * (512 * 9);
            int ic = rem / 9, tap = rem - ic * 9;
            g_wta[((size_t)tap * 128 + oc) * 512 + ic] = tf32r(wa[i]);
        } else if (i < n1 + n2) {
            int j = i - n1;
            int oc = j / (128 * 9);
            int rem = j - oc * (128 * 9);
            int ic = rem / 9, tap = rem - ic * 9;
            g_wtb[((size_t)tap * 128 + oc) * 128 + ic] = tf32r(wb[j]);
        } else if (i < n1 + n2 + n3) {
            int j = i - n1 - n2;
            int oc = j / (640 * 9);
            int rem = j - oc * (640 * 9);
            int ic = rem / 9, tap = rem - ic * 9;
            g_wt1[((size_t)tap * 512 + oc) * 640 + ic] = tf32r(w1[j]);
        } else if (i < n1 + n2 + n3 + n4) {
            int j = i - n1 - n2 - n3;
            g_w2r[j] = tf32r(w2[j]);
        } else if (i < n1 + n2 + n3 + n4 + n5) {
            int j = i - n1 - n2 - n3 - n4;
            int r = j >> 7, ic = j & 127;
            float v = 0.f;
            if (r < 16) v = wq[r * 128 + ic];
            else if (r < 32) v = wk[(r - 16) * 128 + ic];
            else if (r < 160) v = wv[(r - 32) * 128 + ic];
            g_wqkv[j] = tf32r(v);
        } else {
            int r = i - n1 - n2 - n3 - n4 - n5;
            float v = 0.f;
            if (r < 16) v = bq[r];
            else if (r < 32) v = bk[r - 16];
            else if (r < 160) v = bv[r - 32];
            g_bqkv[r] = v;
        }
    }
}

// ---------------- tf32 TC implicit-GEMM conv (+BN+ReLU) ----------------
// CTA: 128 oc x 256 px, 8 warps of 64x64. A perm-K (stride 20); B perm-K
// XOR-swizzled [px][16]. TWO 16-K chunks per barrier (4 slots each buffer).
#define ASTRIDE 20
#define ASTG (128 * ASTRIDE)
#define BSTG (256 * 16)
#define CONV_SMEM ((4 * ASTG + 4 * BSTG) * 4)

template<int NTAPS, bool ROUND>
__global__ void __launch_bounds__(256, 1) conv_tc(
    const float* __restrict__ in1, int cin1,
    const float* __restrict__ in2, int cin2,
    const float* __restrict__ Aw, int OCtot,
    float* __restrict__ outp,
    const float* __restrict__ q0, const float* __restrict__ q1,
    const float* __restrict__ q2, const float* __restrict__ q3)
{
    const int CIN = cin1 + cin2;
    const int NCHUNK = (NTAPS * CIN) / 16;

    extern __shared__ float dsm[];
    float* Asm = dsm;
    float* Bsm = dsm + 4 * ASTG;

    int tid = threadIdx.x, lane = tid & 31, wid = tid >> 5;
    int wm = (wid & 1) * 64, wn = (wid >> 1) * 64;
    int px0 = blockIdx.x * 256;
    int oc0 = blockIdx.y * 128;
    int b = blockIdx.z;
    in1 += (size_t)b * cin1 * NPIX;
    if (cin2 > 0) in2 += (size_t)b * cin2 * NPIX;
    outp += (size_t)b * OCtot * NPIX;

    int arow = tid >> 1, ahalf = tid & 1;
    int px = px0 + tid;
    int ph = px / 96, pw = px - ph * 96;
    int rsw = (tid >> 1) & 3;
    int kq = lane & 3, g4 = lane >> 2;

    float4 pa0, pa1;
    float pb[16];

    auto loadA = [&](int c) {
        int ko = c * 16;
        int tap = (NTAPS == 9) ? ko / CIN : 0;
        int ic = ko - tap * CIN;
        const float* ap = Aw + ((size_t)tap * OCtot + oc0 + arow) * CIN + ic + ahalf * 8;
        pa0 = *(const float4*)ap;
        pa1 = *(const float4*)(ap + 4);
    };
    auto loadB = [&](int c) {
        int ko = c * 16;
        int tap = (NTAPS == 9) ? ko / CIN : 0;
        int ic = ko - tap * CIN;
        const float* src = (ic < cin1) ? (in1 + (size_t)ic * NPIX)
                                       : (in2 + (size_t)(ic - cin1) * NPIX);
        if (NTAPS == 9) {
            int dh = tap / 3 - 1, dw = tap % 3 - 1;
            int hh = ph + dh, ww = pw + dw;
            bool ok = ((unsigned)hh < 96u) && ((unsigned)ww < 96u);
            const float* sp = src + px + dh * 96 + dw;
#pragma unroll
            for (int k = 0; k < 16; k++)
                pb[k] = ok ? __ldg(sp + (size_t)k * NPIX) : 0.f;
        } else {
#pragma unroll
            for (int k = 0; k < 16; k++)
                pb[k] = __ldg(src + (size_t)k * NPIX + px);
        }
    };
    auto storeAB = [&](int sl) {
        float* Ad = Asm + sl * ASTG + arow * ASTRIDE + ahalf * 2;
        float av0[4] = {pa0.x, pa0.y, pa0.z, pa0.w};
        float av1[4] = {pa1.x, pa1.y, pa1.z, pa1.w};
#pragma unroll
        for (int t = 0; t < 4; t++)
            *(float2*)(Ad + t * 4) = make_float2(av0[t], av1[t]);
        float* Bd = Bsm + sl * BSTG + tid * 16;
#pragma unroll
        for (int t = 0; t < 4; t++)
            *(float4*)(Bd + ((t ^ rsw) * 4)) =
                make_float4(pb[t], pb[t + 4], pb[t + 8], pb[t + 12]);
    };

    float acc[4][8][4];
#pragma unroll
    for (int i = 0; i < 4; i++)
#pragma unroll
        for (int j = 0; j < 8; j++)
#pragma unroll
            for (int r = 0; r < 4; r++) acc[i][j][r] = 0.f;

    auto doMMA = [&](int sl) {
        const float* Ab = Asm + sl * ASTG;
        const float* Bb = Bsm + sl * BSTG;
        float4 alo[4], ahi[4], bfr[8];
#pragma unroll
        for (int i = 0; i < 4; i++) {
            int m = wm + i * 16 + g4;
            alo[i] = *(const float4*)(Ab + m * ASTRIDE + kq * 4);
            ahi[i] = *(const float4*)(Ab + (m + 8) * ASTRIDE + kq * 4);
        }
#pragma unroll
        for (int j = 0; j < 8; j++) {
            int n = wn + j * 8 + g4;
            int slot = kq ^ ((n >> 1) & 3);
            bfr[j] = *(const float4*)(Bb + n * 16 + slot * 4);
        }
#pragma unroll
        for (int kk = 0; kk < 2; kk++) {
#pragma unroll
            for (int i = 0; i < 4; i++) {
                uint32_t af[4];
                if (kk == 0) {
                    af[0] = __float_as_uint(alo[i].x); af[1] = __float_as_uint(ahi[i].x);
                    af[2] = __float_as_uint(alo[i].y); af[3] = __float_as_uint(ahi[i].y);
                } else {
                    af[0] = __float_as_uint(alo[i].z); af[1] = __float_as_uint(ahi[i].z);
                    af[2] = __float_as_uint(alo[i].w); af[3] = __float_as_uint(ahi[i].w);
                }
#pragma unroll
                for (int j = 0; j < 8; j++) {
                    uint32_t bu[2];
                    if (kk == 0) { bu[0] = __float_as_uint(bfr[j].x); bu[1] = __float_as_uint(bfr[j].y); }
                    else         { bu[0] = __float_as_uint(bfr[j].z); bu[1] = __float_as_uint(bfr[j].w); }
                    mma1688(acc[i][j], af, bu);
                }
            }
        }
    };

    loadB(0); loadA(0); storeAB(0);
    loadB(1); loadA(1); storeAB(1);
    __syncthreads();

    for (int cc = 0; cc < NCHUNK; cc += 2) {
        int st = (cc >> 1) & 1;
        bool more = (cc + 2 < NCHUNK);
        if (more) { loadB(cc + 2); loadA(cc + 2); }
        doMMA(st * 2 + 0);
        if (more) storeAB((st ^ 1) * 2 + 0);
        if (more) { loadB(cc + 3); loadA(cc + 3); }
        doMMA(st * 2 + 1);
        if (more) storeAB((st ^ 1) * 2 + 1);
        __syncthreads();
    }

#pragma unroll
    for (int i = 0; i < 4; i++) {
#pragma unroll
        for (int hh = 0; hh < 2; hh++) {
            int row = oc0 + wm + i * 16 + g4 + hh * 8;
            float inv = __ldg(q0 + row) * rsqrtf(__ldg(q3 + row) + 1e-5f);
            float add = __ldg(q1 + row) - __ldg(q2 + row) * inv;
#pragma unroll
            for (int j = 0; j < 8; j++) {
                int col = px0 + wn + j * 8 + kq * 2;
                size_t off = (size_t)row * NPIX + col;
                float v0 = fmaxf(acc[i][j][hh * 2 + 0] * inv + add, 0.f);
                float v1 = fmaxf(acc[i][j][hh * 2 + 1] * inv + add, 0.f);
                if (ROUND) { v0 = tf32r(v0); v1 = tf32r(v1); }
                *(float2*)(outp + off) = make_float2(v0, v1);
            }
        }
    }
}

// ---------------- qkv via TC ----------------
__global__ void __launch_bounds__(256, 1) qkv_tc()
{
    __shared__ float Asm[2][64 * ASTRIDE];
    __shared__ float Bsm[2][BSTG];

    int tid = threadIdx.x, lane = tid & 31, wid = tid >> 5;
    int wn = wid * 32;
    int px0 = blockIdx.x * 256;
    int oc0 = blockIdx.y * 64;
    int b = blockIdx.z;
    const float* in = g_out1 + (size_t)b * ICd * NPIX;
    float* outp = g_qkv + (size_t)b * 192 * NPIX;

    int arow = tid >> 1, ahalf = tid & 1;
    int px = px0 + tid;
    int rsw = (tid >> 1) & 3;

    float4 pa0, pa1;
    float pb[16];
    auto loadA = [&](int c) {
        if (tid < 128) {
            const float* ap = g_wqkv + (size_t)(oc0 + arow) * 128 + c * 16 + ahalf * 8;
            pa0 = *(const float4*)ap;
            pa1 = *(const float4*)(ap + 4);
        }
    };
    auto loadB = [&](int c) {
        const float* sp = in + (size_t)(c * 16) * NPIX + px;
#pragma unroll
        for (int k = 0; k < 16; k++)
            pb[k] = __ldg(sp + (size_t)k * NPIX);
    };
    auto storeAB = [&](int s) {
        if (tid < 128) {
            float* Ad = &Asm[s][arow * ASTRIDE + ahalf * 2];
            float av0[4] = {pa0.x, pa0.y, pa0.z, pa0.w};
            float av1[4] = {pa1.x, pa1.y, pa1.z, pa1.w};
#pragma unroll
            for (int t = 0; t < 4; t++)
                *(float2*)(Ad + t * 4) = make_float2(av0[t], av1[t]);
        }
        float* Bd = &Bsm[s][tid * 16];
#pragma unroll
        for (int t = 0; t < 4; t++)
            *(float4*)(Bd + ((t ^ rsw) * 4)) =
                make_float4(pb[t], pb[t + 4], pb[t + 8], pb[t + 12]);
    };

    float acc[4][4][4];
#pragma unroll
    for (int i = 0; i < 4; i++)
#pragma unroll
        for (int j = 0; j < 4; j++)
#pragma unroll
            for (int r = 0; r < 4; r++) acc[i][j][r] = 0.f;

    loadA(0); loadB(0); storeAB(0);
    __syncthreads();

    int kq = lane & 3, g4 = lane >> 2;
    const int NCHUNK = 8;
    for (int c = 0; c < NCHUNK; c++) {
        int s = c & 1;
        if (c + 1 < NCHUNK) { loadA(c + 1); loadB(c + 1); }
        const float* Ab = &Asm[s][0];
        const float* Bb = &Bsm[s][0];
        float4 alo[4], ahi[4], bfr[4];
#pragma unroll
        for (int i = 0; i < 4; i++) {
            int m = i * 16 + g4;
            alo[i] = *(const float4*)(Ab + m * ASTRIDE + kq * 4);
            ahi[i] = *(const float4*)(Ab + (m + 8) * ASTRIDE + kq * 4);
        }
#pragma unroll
        for (int j = 0; j < 4; j++) {
            int n = wn + j * 8 + g4;
            int slot = kq ^ ((n >> 1) & 3);
            bfr[j] = *(const float4*)(Bb + n * 16 + slot * 4);
        }
#pragma unroll
        for (int kk = 0; kk < 2; kk++) {
#pragma unroll
            for (int i = 0; i < 4; i++) {
                uint32_t af[4];
                if (kk == 0) {
                    af[0] = __float_as_uint(alo[i].x); af[1] = __float_as_uint(ahi[i].x);
                    af[2] = __float_as_uint(alo[i].y); af[3] = __float_as_uint(ahi[i].y);
                } else {
                    af[0] = __float_as_uint(alo[i].z); af[1] = __float_as_uint(ahi[i].z);
                    af[2] = __float_as_uint(alo[i].w); af[3] = __float_as_uint(ahi[i].w);
                }
#pragma unroll
                for (int j = 0; j < 4; j++) {
                    uint32_t bu[2];
                    if (kk == 0) { bu[0] = __float_as_uint(bfr[j].x); bu[1] = __float_as_uint(bfr[j].y); }
                    else         { bu[0] = __float_as_uint(bfr[j].z); bu[1] = __float_as_uint(bfr[j].w); }
                    mma1688(acc[i][j], af, bu);
                }
            }
        }
        if (c + 1 < NCHUNK) storeAB(s ^ 1);
        __syncthreads();
    }

#pragma unroll
    for (int i = 0; i < 4; i++) {
#pragma unroll
        for (int hh = 0; hh < 2; hh++) {
            int row = oc0 + i * 16 + g4 + hh * 8;
            float add = g_bqkv[row];
#pragma unroll
            for (int j = 0; j < 4; j++) {
                int col = px0 + wn + j * 8 + kq * 2;
                *(float2*)(outp + (size_t)row * NPIX + col) = make_float2(
                    acc[i][j][hh * 2 + 0] + add, acc[i][j][hh * 2 + 1] + add);
            }
        }
    }
}

// ---------------- final fused: out = W2*bott1 + b2 + att'*xr + x ----------------
__global__ void __launch_bounds__(256, 1) final_tc(
    const float* __restrict__ xexact, const float* __restrict__ b2,
    float* __restrict__ outp)
{
    extern __shared__ float dsm[];
    float* Asm = dsm;
    float* Bsm = dsm + 4 * ASTG;

    int tid = threadIdx.x, lane = tid & 31, wid = tid >> 5;
    int wm = (wid & 1) * 64, wn = (wid >> 1) * 64;
    int px0 = blockIdx.x * 256;
    int oc0 = blockIdx.y * 128;
    int b = blockIdx.z;
    const float* B1 = g_bott1 + (size_t)b * Cc * NPIX;
    const float* B2 = g_xr + (size_t)b * Cc * NPIX;
    const float* A2 = g_energy + (size_t)b * Cc * Cc;
    const float* xb = xexact + (size_t)b * Cc * NPIX;
    outp += (size_t)b * Cc * NPIX;

    int arow = tid >> 1, ahalf = tid & 1;
    int px = px0 + tid;
    int rsw = (tid >> 1) & 3;
    int kq = lane & 3, g4 = lane >> 2;

    float4 pa0, pa1;
    float pb[16];
    auto loadA = [&](int c) {
        int p = c >> 5;
        int ic = (c & 31) * 16;
        const float* base = p ? A2 : g_w2r;
        const float* ap = base + (size_t)(oc0 + arow) * Cc + ic + ahalf * 8;
        pa0 = *(const float4*)ap;
        pa1 = *(const float4*)(ap + 4);
    };
    auto loadB = [&](int c) {
        int p = c >> 5;
        int ic = (c & 31) * 16;
        const float* sp = (p ? B2 : B1) + (size_t)ic * NPIX + px;
#pragma unroll
        for (int k = 0; k < 16; k++)
            pb[k] = __ldg(sp + (size_t)k * NPIX);
    };
    auto storeAB = [&](int sl) {
        float* Ad = Asm + sl * ASTG + arow * ASTRIDE + ahalf * 2;
        float av0[4] = {pa0.x, pa0.y, pa0.z, pa0.w};
        float av1[4] = {pa1.x, pa1.y, pa1.z, pa1.w};
#pragma unroll
        for (int t = 0; t < 4; t++)
            *(float2*)(Ad + t * 4) = make_float2(av0[t], av1[t]);
        float* Bd = Bsm + sl * BSTG + tid * 16;
#pragma unroll
        for (int t = 0; t < 4; t++)
            *(float4*)(Bd + ((t ^ rsw) * 4)) =
                make_float4(pb[t], pb[t + 4], pb[t + 8], pb[t + 12]);
    };

    float acc[4][8][4];
#pragma unroll
    for (int i = 0; i < 4; i++)
#pragma unroll
        for (int j = 0; j < 8; j++)
#pragma unroll
            for (int r = 0; r < 4; r++) acc[i][j][r] = 0.f;

    auto doMMA = [&](int sl) {
        const float* Ab = Asm + sl * ASTG;
        const float* Bb = Bsm + sl * BSTG;
        float4 alo[4], ahi[4], bfr[8];
#pragma unroll
        for (int i = 0; i < 4; i++) {
            int m = wm + i * 16 + g4;
            alo[i] = *(const float4*)(Ab + m * ASTRIDE + kq * 4);
            ahi[i] = *(const float4*)(Ab + (m + 8) * ASTRIDE + kq * 4);
        }
#pragma unroll
        for (int j = 0; j < 8; j++) {
            int n = wn + j * 8 + g4;
            int slot = kq ^ ((n >> 1) & 3);
            bfr[j] = *(const float4*)(Bb + n * 16 + slot * 4);
        }
#pragma unroll
        for (int kk = 0; kk < 2; kk++) {
#pragma unroll
            for (int i = 0; i < 4; i++) {
                uint32_t af[4];
                if (kk == 0) {
                    af[0] = __float_as_uint(alo[i].x); af[1] = __float_as_uint(ahi[i].x);
                    af[2] = __float_as_uint(alo[i].y); af[3] = __float_as_uint(ahi[i].y);
                } else {
                    af[0] = __float_as_uint(alo[i].z); af[1] = __float_as_uint(ahi[i].z);
                    af[2] = __float_as_uint(alo[i].w); af[3] = __float_as_uint(ahi[i].w);
                }
#pragma unroll
                for (int j = 0; j < 8; j++) {
                    uint32_t bu[2];
                    if (kk == 0) { bu[0] = __float_as_uint(bfr[j].x); bu[1] = __float_as_uint(bfr[j].y); }
                    else         { bu[0] = __float_as_uint(bfr[j].z); bu[1] = __float_as_uint(bfr[j].w); }
                    mma1688(acc[i][j], af, bu);
                }
            }
        }
    };

    loadB(0); loadA(0); storeAB(0);
    loadB(1); loadA(1); storeAB(1);
    __syncthreads();

    const int NCHUNK = 64;
    for (int cc = 0; cc < NCHUNK; cc += 2) {
        int st = (cc >> 1) & 1;
        bool more = (cc + 2 < NCHUNK);
        if (more) { loadB(cc + 2); loadA(cc + 2); }
        doMMA(st * 2 + 0);
        if (more) storeAB((st ^ 1) * 2 + 0);
        if (more) { loadB(cc + 3); loadA(cc + 3); }
        doMMA(st * 2 + 1);
        if (more) storeAB((st ^ 1) * 2 + 1);
        __syncthreads();
    }

#pragma unroll
    for (int i = 0; i < 4; i++) {
#pragma unroll
        for (int hh = 0; hh < 2; hh++) {
            int row = oc0 + wm + i * 16 + g4 + hh * 8;
            float add = __ldg(b2 + row);
#pragma unroll
            for (int j = 0; j < 8; j++) {
                int col = px0 + wn + j * 8 + kq * 2;
                size_t off = (size_t)row * NPIX + col;
                float2 xv = *(const float2*)(xb + off);
                *(float2*)(outp + off) = make_float2(
                    acc[i][j][hh * 2 + 0] + add + xv.x,
                    acc[i][j][hh * 2 + 1] + add + xv.y);
            }
        }
    }
}

// ---------------- CAM energy: 3xTF32 TC, symmetric upper-tri blocks, split-K ----------------
__global__ void __launch_bounds__(256, 2) egemm_tc(const float* __restrict__ xexact)
{
    __shared__ float Ah[128][20], Al[128][20], Bh[128][20], Bl[128][20];

    int bz = blockIdx.z;
    int b = bz / ESPLIT, ks = bz - b * ESPLIT;
    const float* X = xexact + (size_t)b * Cc * NPIX;
    float* Cm = g_epart + (size_t)(ks * Bq + b) * Cc * Cc;
    const int KCH = NPIX / ESPLIT;
    int k0s = ks * KCH, k0e = k0s + KCH;

    int pid = blockIdx.x;
    int by = (pid >= 4) + (pid >= 7) + (pid >= 9);
    int base = (by == 0) ? 0 : (by == 1) ? 4 : (by == 2) ? 7 : 9;
    int bx = by + pid - base;

    int tid = threadIdx.x, lane = tid & 31, wid = tid >> 5;
    int wm = (wid & 1) * 64, wn = (wid >> 1) * 32;
    int row0 = by * 128, col0 = bx * 128;
    int ar = tid >> 1, ak = (tid & 1) * 8;
    const float* Arx = X + (size_t)(row0 + ar) * NPIX + ak;
    const float* Brx = X + (size_t)(col0 + ar) * NPIX + ak;

    float acc[4][4][4];
#pragma unroll
    for (int i = 0; i < 4; i++)
#pragma unroll
        for (int j = 0; j < 4; j++)
#pragma unroll
            for (int r = 0; r < 4; r++) acc[i][j][r] = 0.f;

    for (int k0 = k0s; k0 < k0e; k0 += 16) {
        __syncthreads();
#pragma unroll
        for (int half = 0; half < 2; half++) {
            float4 va = *(const float4*)(Arx + k0 + half * 4);
            float4 vb4 = *(const float4*)(Brx + k0 + half * 4);
            float4 h, l;
            h.x = tf32r(va.x); l.x = tf32r(va.x - h.x);
            h.y = tf32r(va.y); l.y = tf32r(va.y - h.y);
            h.z = tf32r(va.z); l.z = tf32r(va.z - h.z);
            h.w = tf32r(va.w); l.w = tf32r(va.w - h.w);
            *(float4*)&Ah[ar][ak + half * 4] = h;
            *(float4*)&Al[ar][ak + half * 4] = l;
            h.x = tf32r(vb4.x); l.x = tf32r(vb4.x - h.x);
            h.y = tf32r(vb4.y); l.y = tf32r(vb4.y - h.y);
            h.z = tf32r(vb4.z); l.z = tf32r(vb4.z - h.z);
            h.w = tf32r(vb4.w); l.w = tf32r(vb4.w - h.w);
            *(float4*)&Bh[ar][ak + half * 4] = h;
            *(float4*)&Bl[ar][ak + half * 4] = l;
        }
        __syncthreads();
#pragma unroll
        for (int kk = 0; kk < 16; kk += 8) {
            int kq = kk + (lane & 3);
            int g4 = lane >> 2;
            uint32_t ah[4][4], al[4][4];
#pragma unroll
            for (int i = 0; i < 4; i++) {
                int m = wm + i * 16 + g4;
                ah[i][0] = __float_as_uint(Ah[m][kq]);
                ah[i][1] = __float_as_uint(Ah[m + 8][kq]);
                ah[i][2] = __float_as_uint(Ah[m][kq + 4]);
                ah[i][3] = __float_as_uint(Ah[m + 8][kq + 4]);
                al[i][0] = __float_as_uint(Al[m][kq]);
                al[i][1] = __float_as_uint(Al[m + 8][kq]);
                al[i][2] = __float_as_uint(Al[m][kq + 4]);
                al[i][3] = __float_as_uint(Al[m + 8][kq + 4]);
            }
#pragma unroll
            for (int j = 0; j < 4; j++) {
                int n = wn + j * 8 + g4;
                uint32_t bh[2], bl[2];
                bh[0] = __float_as_uint(Bh[n][kq]);
                bh[1] = __float_as_uint(Bh[n][kq + 4]);
                bl[0] = __float_as_uint(Bl[n][kq]);
                bl[1] = __float_as_uint(Bl[n][kq + 4]);
#pragma unroll
                for (int i = 0; i < 4; i++) {
                    mma1688(acc[i][j], ah[i], bh);
                    mma1688(acc[i][j], ah[i], bl);
                    mma1688(acc[i][j], al[i], bh);
                }
            }
        }
    }

#pragma unroll
    for (int i = 0; i < 4; i++) {
#pragma unroll
        for (int hh = 0; hh < 2; hh++) {
            int row = row0 + wm + i * 16 + (lane >> 2) + hh * 8;
#pragma unroll
            for (int j = 0; j < 4; j++) {
                int col = col0 + wn + j * 8 + (lane & 3) * 2;
                *(float2*)&Cm[(size_t)row * Cc + col] = make_float2(
                    acc[i][j][hh * 2 + 0], acc[i][j][hh * 2 + 1]);
            }
        }
    }
}

// ---------------- criss-cross attention (barrier-free channel loop) ----------------
__global__ void __launch_bounds__(192) cca2_kernel(const float* __restrict__ gamma)
{
    extern __shared__ float sm[];
    float* e = sm;
    float* qs = sm + 192 * 96;
    float* ks_ = qs + 16 * 96;

    int h = blockIdx.x, b = blockIdx.y;
    int tid = threadIdx.x;
    const float* qb = g_qkv + (size_t)b * 192 * NPIX;
    const float* kb = qb + (size_t)16 * NPIX;
    const float* vb = qb + (size_t)32 * NPIX;

    for (int idx = tid; idx < 16 * 96; idx += 192) {
        int c = idx / 96, w = idx - c * 96;
        qs[c * 96 + w] = qb[c * NPIX + h * Wd + w];
        ks_[c * 96 + w] = kb[c * NPIX + h * Wd + w];
    }
    __syncthreads();
    for (int idx = tid; idx < 96 * 96; idx += 192) {
        int s = idx / 96, w = idx - s * 96;
        float a = 0.f;
#pragma unroll
        for (int c = 0; c < 16; c++) a += qs[c * 96 + w] * ks_[c * 96 + s];
        e[(96 + s) * 96 + w] = a;
    }
    for (int idx = tid; idx < 96 * 96; idx += 192) {
        int s = idx / 96, w = idx - s * 96;
        float a = 0.f;
#pragma unroll
        for (int c = 0; c < 16; c++) a += qs[c * 96 + w] * kb[c * NPIX + s * Wd + w];
        e[s * 96 + w] = (s == h) ? -1e30f : a;
    }
    __syncthreads();
    if (tid < 96) {
        int w = tid;
        float M = -1e30f;
        for (int i = 0; i < 192; i++) M = fmaxf(M, e[i * 96 + w]);
        float S = 0.f;
        for (int i = 0; i < 192; i++) {
            float p = __expf(e[i * 96 + w] - M);
            e[i * 96 + w] = p; S += p;
        }
        float inv = 1.f / S;
        for (int i = 0; i < 192; i++) e[i * 96 + w] *= inv;
    }
    __syncthreads();
    int g = tid / 96;
    int w = tid - g * 96;
    float gam = __ldg(gamma);
    for (int cc = 0; cc < 64; cc++) {
        int c = g * 64 + cc;
        const float* vcol = vb + (size_t)c * NPIX + w;
        const float* vrow = vb + (size_t)c * NPIX + h * 96;
        float oH = 0.f, oW = 0.f;
#pragma unroll 4
        for (int s = 0; s < 96; s++) {
            oH += vcol[s * Wd] * e[s * 96 + w];
            oW += __ldg(vrow + s) * e[(96 + s) * 96 + w];
        }
        size_t o = ((size_t)b * ICd + c) * NPIX + h * Wd + w;
        g_cca[o] = tf32r(gam * (oH + oW) + g_out1[o]);
    }
}

// ---------------- CAM softmax (sums partials incl. transposed lower blocks) ----------------
__global__ void __launch_bounds__(128) cam_softmax_kernel(const float* __restrict__ gma)
{
    int b = blockIdx.y, c = blockIdx.x;
    int t = threadIdx.x;
    __shared__ float red[4];

    int br = c >> 7;
    int bc = t >> 5;

    float4 v = make_float4(0.f, 0.f, 0.f, 0.f);
    if (bc >= br) {
#pragma unroll
        for (int s = 0; s < ESPLIT; s++) {
            const float4 p = *(const float4*)&g_epart[(((size_t)(s * Bq + b)) * Cc + c) * Cc + t * 4];
            v.x += p.x; v.y += p.y; v.z += p.z; v.w += p.w;
        }
    } else {
#pragma unroll
        for (int s = 0; s < ESPLIT; s++) {
            const float* basep = g_epart + ((size_t)(s * Bq + b)) * Cc * Cc;
            v.x += basep[(size_t)(t * 4 + 0) * Cc + c];
            v.y += basep[(size_t)(t * 4 + 1) * Cc + c];
            v.z += basep[(size_t)(t * 4 + 2) * Cc + c];
            v.w += basep[(size_t)(t * 4 + 3) * Cc + c];
        }
    }

    float lmn = fminf(fminf(v.x, v.y), fminf(v.z, v.w));
#pragma unroll
    for (int o = 16; o; o >>= 1) lmn = fminf(lmn, __shfl_xor_sync(0xffffffffu, lmn, o));
    if ((t & 31) == 0) red[t >> 5] = lmn;
    __syncthreads();
    float mn = fminf(fminf(red[0], red[1]), fminf(red[2], red[3]));
    __syncthreads();
    float4 p;
    p.x = __expf(mn - v.x); p.y = __expf(mn - v.y);
    p.z = __expf(mn - v.z); p.w = __expf(mn - v.w);
    float ls = p.x + p.y + p.z + p.w;
#pragma unroll
    for (int o = 16; o; o >>= 1) ls += __shfl_xor_sync(0xffffffffu, ls, o);
    if ((t & 31) == 0) red[t >> 5] = ls;
    __syncthreads();
    float gam = __ldg(gma);
    float inv = gam / (red[0] + red[1] + red[2] + red[3]);
    p.x = tf32r(p.x * inv); p.y = tf32r(p.y * inv);
    p.z = tf32r(p.z * inv); p.w = tf32r(p.w * inv);
    *(float4*)&g_energy[((size_t)b * Cc + c) * Cc + t * 4] = p;
}

// ---------------- launch ----------------
extern "C" void kernel_launch(void* const* d_in, const int* in_sizes, int n_in,
                              void* d_out, int out_size)
{
    const float* x        = (const float*)d_in[0];
    const float* conva_w  = (const float*)d_in[1];
    const float* bn1_s    = (const float*)d_in[2];
    const float* bn1_b    = (const float*)d_in[3];
    const float* bn1_m    = (const float*)d_in[4];
    const float* bn1_v    = (const float*)d_in[5];
    const float* wq       = (const float*)d_in[6];
    const float* bq       = (const float*)d_in[7];
    const float* wk       = (const float*)d_in[8];
    const float* bk       = (const float*)d_in[9];
    const float* wv       = (const float*)d_in[10];
    const float* bv       = (const float*)d_in[11];
    const float* gamma_cca= (const float*)d_in[12];
    const float* convb_w  = (const float*)d_in[13];
    const float* bn2_s    = (const float*)d_in[14];
    const float* bn2_b    = (const float*)d_in[15];
    const float* bn2_m    = (const float*)d_in[16];
    const float* bn2_v    = (const float*)d_in[17];
    const float* bot_w1   = (const float*)d_in[18];
    const float* bn3_s    = (const float*)d_in[19];
    const float* bn3_b    = (const float*)d_in[20];
    const float* bn3_m    = (const float*)d_in[21];
    const float* bn3_v    = (const float*)d_in[22];
    const float* bot_w2   = (const float*)d_in[23];
    const float* bot_b2   = (const float*)d_in[24];
    const float* gamma_cam= (const float*)d_in[25];
    float* out = (float*)d_out;

    float *p_xr, *p_cca, *p_b1, *p_wta, *p_wtb, *p_wt1, *p_out1, *p_out2;
    cudaGetSymbolAddress((void**)&p_xr, g_xr);
    cudaGetSymbolAddress((void**)&p_cca, g_cca);
    cudaGetSymbolAddress((void**)&p_b1, g_bott1);
    cudaGetSymbolAddress((void**)&p_wta, g_wta);
    cudaGetSymbolAddress((void**)&p_wtb, g_wtb);
    cudaGetSymbolAddress((void**)&p_wt1, g_wt1);
    cudaGetSymbolAddress((void**)&p_out1, g_out1);
    cudaGetSymbolAddress((void**)&p_out2, g_out2);

    cudaFuncSetAttribute(cca2_kernel, cudaFuncAttributeMaxDynamicSharedMemorySize, 90112);
    cudaFuncSetAttribute(conv_tc<9, true>, cudaFuncAttributeMaxDynamicSharedMemorySize, CONV_SMEM);
    cudaFuncSetAttribute(final_tc, cudaFuncAttributeMaxDynamicSharedMemorySize, CONV_SMEM);

    // side stream + fork/join events (created per call; host-side only, tiny,
    // and kernel_launch runs only a handful of times outside graph replay)
    cudaStream_t s2;
    cudaEvent_t evFork, evJoin;
    cudaStreamCreateWithFlags(&s2, cudaStreamNonBlocking);
    cudaEventCreateWithFlags(&evFork, cudaEventDisableTiming);
    cudaEventCreateWithFlags(&evJoin, cudaEventDisableTiming);

    // fork: CAM branch depends only on x
    cudaEventRecord(evFork, 0);
    cudaStreamWaitEvent(s2, evFork, 0);

    // side stream: CAM energy (symmetric, split-K=8) + softmax
    egemm_tc<<<dim3(10, 1, Bq * ESPLIT), 256, 0, s2>>>(x);
    cam_softmax_kernel<<<dim3(Cc, Bq), 128, 0, s2>>>(gamma_cam);
    cudaEventRecord(evJoin, s2);

    // main stream: prep + conv chain
    roundcopy4<<<512, 256>>>(x, p_xr, Bq * Cc * NPIX / 4);
    prep_weights<<<512, 256>>>(conva_w, convb_w, bot_w1, bot_w2,
                               wq, bq, wk, bk, wv, bv);

    conv_tc<9, true><<<dim3(36, 1, Bq), 256, CONV_SMEM>>>(
        p_xr, Cc, nullptr, 0, p_wta, ICd, p_out1,
        bn1_s, bn1_b, bn1_m, bn1_v);

    qkv_tc<<<dim3(36, 3, Bq), 256>>>();

    cca2_kernel<<<dim3(Hd, Bq), 192, 90112>>>(gamma_cca);

    conv_tc<9, true><<<dim3(36, 1, Bq), 256, CONV_SMEM>>>(
        p_cca, ICd, nullptr, 0, p_wtb, ICd, p_out2,
        bn2_s, bn2_b, bn2_m, bn2_v);

    conv_tc<9, true><<<dim3(36, 4, Bq), 256, CONV_SMEM>>>(
        p_xr, Cc, p_out2, ICd, p_wt1, Cc, p_b1,
        bn3_s, bn3_b, bn3_m, bn3_v);

    // join: final needs bott1 (main) + energy (side) + xr
    cudaStreamWaitEvent(0, evJoin, 0);
    final_tc<<<dim3(36, 4, Bq), 256, CONV_SMEM>>>(x, bot_b2, out);
}